// round 14
// baseline (speedup 1.0000x reference)
#include <cuda_runtime.h>
#include <cuda_bf16.h>
#include <math.h>

#define NA 8192
#define NB 32
#define NK 128
#define ND 128

__device__ float g_c[NA * NK];
__device__ float g_s[NA * NK];
__device__ float g_F[NB * NK * ND];
__device__ float g_FSre[NB * NK * ND];
__device__ float g_FSim[NB * NK * ND];
__device__ float g_pre[4][NB * NK * ND];   // segsum partials (re)
__device__ float g_pim[4][NB * NK * ND];   // segsum partials (im)
__device__ int   g_seg[NB + 1];

struct DevPtrs {
    const void *kv, *pos, *h, *W1, *b1, *W2, *b2, *W3, *b3, *batch;
    int isbf16;
    int batch64;
};
__device__ DevPtrs g_P;

__device__ __forceinline__ float ldf(const void* p, long i, int isbf) {
    if (isbf) return __bfloat162float(((const __nv_bfloat16*)p)[i]);
    return ((const float*)p)[i];
}
__device__ __forceinline__ int ldb(const void* p, int i, int b64) {
    if (b64) return (int)(((const long long*)p)[i]);
    return ((const int*)p)[i];
}
__device__ __forceinline__ float gelu_t(float x) {
    float x3 = x * x * x;
    return 0.5f * x * (1.0f + tanhf(0.7978845608028654f * fmaf(0.044715f, x3, x)));
}
__device__ static bool is_b32(const int* w) {
    int prev = -1;
    for (int j = 0; j < 128; j++) {
        int v = w[j];
        if (v < 0 || v > 63 || v < prev) return false;
        prev = v;
    }
    return true;
}
__device__ static bool is_b64(const int* w) {
    int prev = -1;
    for (int j = 0; j < 64; j++) {
        int lo = w[2*j], hi = w[2*j+1];
        if (hi != 0 || lo < 0 || lo > 63 || lo < prev) return false;
        prev = lo;
    }
    return true;
}

__global__ void setup_kernel(const void* kv, const void* pos, const void* h,
                             const void* W1, const void* b1, const void* b2,
                             const void* b3, const void* c0, const void* c1,
                             const void* c2, const void* batch_direct, int mf) {
    int tid = threadIdx.x;
    if (tid == 0) {
        DevPtrs P;
        P.kv = kv; P.pos = pos; P.h = h; P.W1 = W1;
        P.b1 = b1; P.b2 = b2; P.b3 = b3;
        const void* batch = batch_direct;
        const void* w2 = c0; const void* w3 = c1;
        if (!batch) {
            const void* cand[3] = {c0, c1, c2};
            int bi = -1;
            for (int i = 0; i < 3; i++) {
                const int* w = (const int*)cand[i];
                if (is_b32(w) || is_b64(w)) { bi = i; break; }
            }
            if (bi < 0) bi = 2;
            int nw = 0; const void* ws[2] = {0, 0};
            for (int i = 0; i < 3; i++) if (i != bi) ws[nw++] = cand[i];
            w2 = ws[0]; w3 = ws[1]; batch = cand[bi];
        }
        P.W2 = w2; P.W3 = w3; P.batch = batch;
        const int* bw = (const int*)batch;
        P.batch64 = (is_b64(bw) && !is_b32(bw)) ? 1 : 0;
        if (mf == 2) P.isbf16 = 1;
        else if (mf == 4) P.isbf16 = 0;
        else {
            const unsigned short* p16 = (const unsigned short*)pos;
            int hits = 0;
            for (int i = 0; i < 256; i++) {
                int e = (p16[i] >> 7) & 0xFF;
                if (e >= 110 && e <= 135) hits++;
            }
            P.isbf16 = (hits > 205);
        }
        g_P = P;
    }
    __syncthreads();
    if (tid <= NB) {
        const void* batch = g_P.batch;
        int b64 = g_P.batch64;
        int lo = 0, hi = NA;
        while (lo < hi) {
            int m = (lo + hi) >> 1;
            if (ldb(batch, m, b64) < tid) lo = m + 1; else hi = m;
        }
        if (lo < 0) lo = 0;
        if (lo > NA) lo = NA;
        g_seg[tid] = lo;
    }
}

__global__ void zero_kernel(unsigned int* out, long words) {
    long i = blockIdx.x * (long)blockDim.x + threadIdx.x;
    if (i < words) out[i] = 0u;
}

// ---------------------------------------------------------------------------
// theta: 2 atoms per block, 256 threads, MUFU sincos
// ---------------------------------------------------------------------------
__global__ void __launch_bounds__(256) theta_kernel() {
    const DevPtrs P = g_P;
    int n0 = blockIdx.x * 2;
    int tid = threadIdx.x;
    int a = tid >> 7;
    int k = tid & 127;
    __shared__ float p[2][3];
    __shared__ int bsh[2];
    if (tid < 6) p[tid / 3][tid % 3] = ldf(P.pos, (long)n0 * 3 + tid, P.isbf16);
    if (tid < 2) bsh[tid] = ldb(P.batch, n0 + tid, P.batch64) & 31;
    __syncthreads();
    int n = n0 + a;
    long base = ((long)bsh[a] * NK + k) * 3;
    float th = fmaf(p[a][0], ldf(P.kv, base, P.isbf16),
               fmaf(p[a][1], ldf(P.kv, base + 1, P.isbf16),
                    p[a][2] * ldf(P.kv, base + 2, P.isbf16)));
    float sv, cv;
    __sincosf(th, &sv, &cv);
    g_c[n * NK + k] = cv;
    g_s[n * NK + k] = sv;
}

// ---------------------------------------------------------------------------
// MLP v4: 8 rows/block, 512 blocks, 256 threads
// ---------------------------------------------------------------------------
#define MROWS 8
__global__ void __launch_bounds__(256) mlp_kernel() {
    __shared__ float a1[MROWS][NK];
    __shared__ float a2[MROWS][NK];
    __shared__ float kvs[MROWS * 3];

    const DevPtrs P = g_P;
    int isbf = P.isbf16;
    int row0 = blockIdx.x * MROWS;
    int tid = threadIdx.x;
    int t = tid & 127;
    int g = tid >> 7;

    if (tid < MROWS * 3) kvs[tid] = ldf(P.kv, (long)row0 * 3 + tid, isbf);

    float w10 = ldf(P.W1, t, isbf);
    float w11 = ldf(P.W1, NK + t, isbf);
    float w12 = ldf(P.W1, 2 * NK + t, isbf);
    float bv1 = ldf(P.b1, t, isbf);
    __syncthreads();
#pragma unroll
    for (int r = 0; r < 4; r++) {
        int row = g * 4 + r;
        float x = fmaf(kvs[row*3], w10, fmaf(kvs[row*3+1], w11,
                  fmaf(kvs[row*3+2], w12, bv1)));
        a1[row][t] = gelu_t(x);
    }
    __syncthreads();
    {
        float y[4];
        float bv = ldf(P.b2, t, isbf);
#pragma unroll
        for (int r = 0; r < 4; r++) y[r] = bv;
        for (int j = 0; j < NK; j += 8) {
            float w0 = ldf(P.W2, (long)j * NK + t, isbf);
            float w1 = ldf(P.W2, (long)(j+1) * NK + t, isbf);
            float w2 = ldf(P.W2, (long)(j+2) * NK + t, isbf);
            float w3 = ldf(P.W2, (long)(j+3) * NK + t, isbf);
            float w4 = ldf(P.W2, (long)(j+4) * NK + t, isbf);
            float w5 = ldf(P.W2, (long)(j+5) * NK + t, isbf);
            float w6 = ldf(P.W2, (long)(j+6) * NK + t, isbf);
            float w7 = ldf(P.W2, (long)(j+7) * NK + t, isbf);
#pragma unroll
            for (int r = 0; r < 4; r++) {
                float4 aL = *(const float4*)&a1[g*4 + r][j];
                float4 aH = *(const float4*)&a1[g*4 + r][j+4];
                y[r] = fmaf(aL.x, w0, y[r]);
                y[r] = fmaf(aL.y, w1, y[r]);
                y[r] = fmaf(aL.z, w2, y[r]);
                y[r] = fmaf(aL.w, w3, y[r]);
                y[r] = fmaf(aH.x, w4, y[r]);
                y[r] = fmaf(aH.y, w5, y[r]);
                y[r] = fmaf(aH.z, w6, y[r]);
                y[r] = fmaf(aH.w, w7, y[r]);
            }
        }
#pragma unroll
        for (int r = 0; r < 4; r++) a2[g*4 + r][t] = gelu_t(y[r]);
    }
    __syncthreads();
    {
        float y[4];
        float bv = ldf(P.b3, t, isbf);
#pragma unroll
        for (int r = 0; r < 4; r++) y[r] = bv;
        for (int j = 0; j < NK; j += 8) {
            float w0 = ldf(P.W3, (long)j * NK + t, isbf);
            float w1 = ldf(P.W3, (long)(j+1) * NK + t, isbf);
            float w2 = ldf(P.W3, (long)(j+2) * NK + t, isbf);
            float w3 = ldf(P.W3, (long)(j+3) * NK + t, isbf);
            float w4 = ldf(P.W3, (long)(j+4) * NK + t, isbf);
            float w5 = ldf(P.W3, (long)(j+5) * NK + t, isbf);
            float w6 = ldf(P.W3, (long)(j+6) * NK + t, isbf);
            float w7 = ldf(P.W3, (long)(j+7) * NK + t, isbf);
#pragma unroll
            for (int r = 0; r < 4; r++) {
                float4 aL = *(const float4*)&a2[g*4 + r][j];
                float4 aH = *(const float4*)&a2[g*4 + r][j+4];
                y[r] = fmaf(aL.x, w0, y[r]);
                y[r] = fmaf(aL.y, w1, y[r]);
                y[r] = fmaf(aL.z, w2, y[r]);
                y[r] = fmaf(aL.w, w3, y[r]);
                y[r] = fmaf(aH.x, w4, y[r]);
                y[r] = fmaf(aH.y, w5, y[r]);
                y[r] = fmaf(aH.z, w6, y[r]);
                y[r] = fmaf(aH.w, w7, y[r]);
            }
        }
#pragma unroll
        for (int r = 0; r < 4; r++)
            g_F[(long)(row0 + g*4 + r) * NK + t] = y[r];
    }
}

// ---------------------------------------------------------------------------
// segsum stage A: grid (NB, 4 kchunks, 4 atom-splits) = 512 blocks, 512 thr.
// Thread owns 4d x 2k. Partials to g_pre/g_pim[sp] (no F multiply).
// ---------------------------------------------------------------------------
__global__ void __launch_bounds__(512) segsumA_kernel() {
    const DevPtrs P = g_P;
    int isbf = P.isbf16;
    int b = blockIdx.x;
    int k0 = blockIdx.y * 32;
    int sp = blockIdx.z;
    int tid = threadIdx.x;
    int d0 = (tid & 31) * 4;
    int kq = tid >> 5;
    int s0 = g_seg[b], s1 = g_seg[b + 1];
    if (s1 < s0) s1 = s0;
    int len = s1 - s0;
    int q0 = s0 + (len * sp) / 4;
    int q1 = s0 + (len * (sp + 1)) / 4;

    __shared__ float csh[32][32], ssh[32][32];
    __shared__ float hsh[32][ND];

    float aR[2][4], aI[2][4];
#pragma unroll
    for (int j = 0; j < 2; j++)
#pragma unroll
        for (int i = 0; i < 4; i++) { aR[j][i] = 0.f; aI[j][i] = 0.f; }

    for (int n0 = q0; n0 < q1; n0 += 32) {
        int cnt = min(32, q1 - n0);
        for (int i = tid; i < cnt * 32; i += 512) {
            int a = i >> 5, kk = i & 31;
            csh[a][kk] = g_c[(n0 + a) * NK + k0 + kk];
            ssh[a][kk] = g_s[(n0 + a) * NK + k0 + kk];
        }
        if (isbf) {
            for (int i = tid; i < cnt * ND; i += 512) {
                int a = i >> 7, d = i & 127;
                hsh[a][d] = __bfloat162float(((const __nv_bfloat16*)P.h)[(long)(n0 + a) * ND + d]);
            }
        } else {
            const float4* h4 = (const float4*)P.h;
            for (int i = tid; i < cnt * 32; i += 512) {
                int a = i >> 5, dq = i & 31;
                ((float4*)&hsh[a][0])[dq] = h4[(long)(n0 + a) * 32 + dq];
            }
        }
        __syncthreads();
#pragma unroll 2
        for (int a = 0; a < cnt; a++) {
            float4 hv = *(const float4*)&hsh[a][d0];
            float c0v = csh[a][kq*2],     s0v = ssh[a][kq*2];
            float c1v = csh[a][kq*2 + 1], s1v = ssh[a][kq*2 + 1];
            aR[0][0] = fmaf(c0v, hv.x, aR[0][0]); aI[0][0] = fmaf(-s0v, hv.x, aI[0][0]);
            aR[0][1] = fmaf(c0v, hv.y, aR[0][1]); aI[0][1] = fmaf(-s0v, hv.y, aI[0][1]);
            aR[0][2] = fmaf(c0v, hv.z, aR[0][2]); aI[0][2] = fmaf(-s0v, hv.z, aI[0][2]);
            aR[0][3] = fmaf(c0v, hv.w, aR[0][3]); aI[0][3] = fmaf(-s0v, hv.w, aI[0][3]);
            aR[1][0] = fmaf(c1v, hv.x, aR[1][0]); aI[1][0] = fmaf(-s1v, hv.x, aI[1][0]);
            aR[1][1] = fmaf(c1v, hv.y, aR[1][1]); aI[1][1] = fmaf(-s1v, hv.y, aI[1][1]);
            aR[1][2] = fmaf(c1v, hv.z, aR[1][2]); aI[1][2] = fmaf(-s1v, hv.z, aI[1][2]);
            aR[1][3] = fmaf(c1v, hv.w, aR[1][3]); aI[1][3] = fmaf(-s1v, hv.w, aI[1][3]);
        }
        __syncthreads();
    }
#pragma unroll
    for (int j = 0; j < 2; j++) {
        long off = ((long)b * NK + k0 + kq*2 + j) * ND + d0;
        *(float4*)&g_pre[sp][off] = make_float4(aR[j][0], aR[j][1], aR[j][2], aR[j][3]);
        *(float4*)&g_pim[sp][off] = make_float4(aI[j][0], aI[j][1], aI[j][2], aI[j][3]);
    }
}

// ---------------------------------------------------------------------------
// segsum stage B: reduce 4 partials + F multiply -> FSre/FSim
// ---------------------------------------------------------------------------
__global__ void __launch_bounds__(256) fsred_kernel() {
    long i = (blockIdx.x * 256L + threadIdx.x);     // float4 index
    if (i >= (long)NB * NK * ND / 4) return;
    const float4* p0 = (const float4*)g_pre[0];
    const float4* p1 = (const float4*)g_pre[1];
    const float4* p2 = (const float4*)g_pre[2];
    const float4* p3 = (const float4*)g_pre[3];
    const float4* q0 = (const float4*)g_pim[0];
    const float4* q1 = (const float4*)g_pim[1];
    const float4* q2 = (const float4*)g_pim[2];
    const float4* q3 = (const float4*)g_pim[3];
    float4 a = p0[i], b = p1[i], c = p2[i], d = p3[i];
    float4 r = make_float4(a.x+b.x+c.x+d.x, a.y+b.y+c.y+d.y,
                           a.z+b.z+c.z+d.z, a.w+b.w+c.w+d.w);
    a = q0[i]; b = q1[i]; c = q2[i]; d = q3[i];
    float4 m = make_float4(a.x+b.x+c.x+d.x, a.y+b.y+c.y+d.y,
                           a.z+b.z+c.z+d.z, a.w+b.w+c.w+d.w);
    float4 f = ((const float4*)g_F)[i];
    ((float4*)g_FSre)[i] = make_float4(f.x*r.x, f.y*r.y, f.z*r.z, f.w*r.w);
    ((float4*)g_FSim)[i] = make_float4(f.x*m.x, f.y*m.y, f.z*m.z, f.w*m.w);
}

// ---------------------------------------------------------------------------
// out v4: grid (NB, 16) = 512 blocks, 256 threads, 16-atom tiles,
// thread owns 2a x 4d, k unrolled x4 with float4 LDS of c/s.
// ---------------------------------------------------------------------------
__global__ void __launch_bounds__(256) out_kernel(void* __restrict__ outp,
                                                  int mode, long cap) {
    int b = blockIdx.x;
    int s0 = g_seg[b], s1 = g_seg[b + 1];
    if (s1 < s0) s1 = s0;
    int tid = threadIdx.x;
    int d0 = (tid & 31) * 4;
    int a0 = (tid >> 5) * 2;          // 8 warps x 2 atoms = 16

    __shared__ float csh[16][NK], ssh[16][NK];

    const float4* FR4 = (const float4*)(g_FSre + (long)b * NK * ND);
    const float4* FI4 = (const float4*)(g_FSim + (long)b * NK * ND);
    int dq = d0 >> 2;

    for (int n0 = s0 + blockIdx.y * 16; n0 < s1; n0 += 16 * 16) {
        int cnt = min(16, s1 - n0);
        for (int i = tid; i < cnt * 32; i += 256) {
            int a = i >> 5, kk = i & 31;
            ((float4*)&csh[a][0])[kk] = *(const float4*)&g_c[(n0 + a) * NK + kk*4];
            ((float4*)&ssh[a][0])[kk] = *(const float4*)&g_s[(n0 + a) * NK + kk*4];
        }
        __syncthreads();

        if (mode == 0) {
            float oR[2][4];
#pragma unroll
            for (int u = 0; u < 2; u++)
#pragma unroll
                for (int i = 0; i < 4; i++) oR[u][i] = 0.f;
            for (int k = 0; k < NK; k += 4) {
                float4 ca = *(const float4*)&csh[a0][k];
                float4 sa = *(const float4*)&ssh[a0][k];
                float4 cb = *(const float4*)&csh[a0+1][k];
                float4 sb = *(const float4*)&ssh[a0+1][k];
#pragma unroll
                for (int kk = 0; kk < 4; kk++) {
                    float4 fr = FR4[(k + kk) * 32 + dq];
                    float4 fi = FI4[(k + kk) * 32 + dq];
                    float cav = kk==0?ca.x:kk==1?ca.y:kk==2?ca.z:ca.w;
                    float sav = kk==0?sa.x:kk==1?sa.y:kk==2?sa.z:sa.w;
                    float cbv = kk==0?cb.x:kk==1?cb.y:kk==2?cb.z:cb.w;
                    float sbv = kk==0?sb.x:kk==1?sb.y:kk==2?sb.z:sb.w;
                    oR[0][0] = fmaf(cav, fr.x, fmaf(-sav, fi.x, oR[0][0]));
                    oR[0][1] = fmaf(cav, fr.y, fmaf(-sav, fi.y, oR[0][1]));
                    oR[0][2] = fmaf(cav, fr.z, fmaf(-sav, fi.z, oR[0][2]));
                    oR[0][3] = fmaf(cav, fr.w, fmaf(-sav, fi.w, oR[0][3]));
                    oR[1][0] = fmaf(cbv, fr.x, fmaf(-sbv, fi.x, oR[1][0]));
                    oR[1][1] = fmaf(cbv, fr.y, fmaf(-sbv, fi.y, oR[1][1]));
                    oR[1][2] = fmaf(cbv, fr.z, fmaf(-sbv, fi.z, oR[1][2]));
                    oR[1][3] = fmaf(cbv, fr.w, fmaf(-sbv, fi.w, oR[1][3]));
                }
            }
#pragma unroll
            for (int u = 0; u < 2; u++) {
                int a = a0 + u;
                if (a < cnt) {
                    long idx = (long)(n0 + a) * ND + d0;
                    if (idx + 4 <= cap)
                        *(float4*)((float*)outp + idx) =
                            make_float4(oR[u][0], oR[u][1], oR[u][2], oR[u][3]);
                }
            }
        } else {
            float oR[2][4], oI[2][4];
#pragma unroll
            for (int u = 0; u < 2; u++)
#pragma unroll
                for (int i = 0; i < 4; i++) { oR[u][i] = 0.f; oI[u][i] = 0.f; }
            for (int k = 0; k < NK; k++) {
                float4 fr = FR4[k * 32 + dq];
                float4 fi = FI4[k * 32 + dq];
#pragma unroll
                for (int u = 0; u < 2; u++) {
                    float c = csh[a0 + u][k];
                    float s = ssh[a0 + u][k];
                    oR[u][0] = fmaf(c, fr.x, fmaf(-s, fi.x, oR[u][0]));
                    oR[u][1] = fmaf(c, fr.y, fmaf(-s, fi.y, oR[u][1]));
                    oR[u][2] = fmaf(c, fr.z, fmaf(-s, fi.z, oR[u][2]));
                    oR[u][3] = fmaf(c, fr.w, fmaf(-s, fi.w, oR[u][3]));
                    oI[u][0] = fmaf(s, fr.x, fmaf(c, fi.x, oI[u][0]));
                    oI[u][1] = fmaf(s, fr.y, fmaf(c, fi.y, oI[u][1]));
                    oI[u][2] = fmaf(s, fr.z, fmaf(c, fi.z, oI[u][2]));
                    oI[u][3] = fmaf(s, fr.w, fmaf(c, fi.w, oI[u][3]));
                }
            }
            for (int u = 0; u < 2; u++) {
                int a = a0 + u;
                if (a < cnt) {
                    long row = (long)(n0 + a) * ND;
                    for (int i = 0; i < 4; i++) {
                        long idx = row + d0 + i;
                        if (mode == 1) {
                            if (2 * idx + 1 < cap)
                                ((float2*)outp)[idx] = make_float2(oR[u][i], oI[u][i]);
                        } else {
                            if (idx + 1 <= cap) {
                                __nv_bfloat162 v;
                                v.x = __float2bfloat16(oR[u][i]);
                                v.y = __float2bfloat16(oI[u][i]);
                                ((__nv_bfloat162*)outp)[idx] = v;
                            }
                        }
                    }
                }
            }
        }
        __syncthreads();
    }
}

// ---------------------------------------------------------------------------
extern "C" void kernel_launch(void* const* d_in, const int* in_sizes, int n_in,
                              void* d_out, int out_size) {
    long mx = 0;
    for (int i = 0; i < n_in; i++) if ((long)in_sizes[i] > mx) mx = in_sizes[i];
    long mf;
    if (mx == 1048576L) mf = 1;
    else if (mx == 2097152L) mf = 2;
    else if (mx == 4194304L) mf = 4;
    else return;

    const void *kv = 0, *pos = 0, *h = 0, *W1 = 0;
    const void* bias[3] = {0, 0, 0};
    const void* grp[3] = {0, 0, 0};
    const void* extra = 0;
    int nb = 0, ng = 0;
    long extra_sz = (mf == 1) ? 8192 : (mf == 2) ? 65536 : 32768;
    for (int i = 0; i < n_in; i++) {
        long s = in_sizes[i];
        const void* p = d_in[i];
        if (s == 12288L * mf)        kv = p;
        else if (s == 24576L * mf)   pos = p;
        else if (s == 1048576L * mf) h = p;
        else if (s == 384L * mf)     W1 = p;
        else if (s == 128L * mf)   { if (nb < 3) bias[nb++] = p; }
        else if (s == 16384L * mf) { if (ng < 3) grp[ng++] = p; }
        else if (s == extra_sz)      extra = p;
    }
    if (!kv || !pos || !h || !W1 || nb < 3) return;

    const void *c0 = 0, *c1 = 0, *c2 = 0, *bd = 0;
    if (ng == 3)               { c0 = grp[0]; c1 = grp[1]; c2 = grp[2]; }
    else if (ng == 2 && extra) { c0 = grp[0]; c1 = grp[1]; bd = extra; }
    else return;

    int mode; long cap;
    if (out_size == 1048576)      { mode = 0; cap = 1048576L; }
    else if (out_size == 2097152) { mode = 1; cap = 2097152L; }
    else if (out_size == 8388608) { mode = 1; cap = 2097152L; }
    else if (out_size == 4194304) { mode = 2; cap = 1048576L; }
    else                          { mode = 0; cap = (long)out_size / 4; }

    if (mode != 0) {
        long words = (long)out_size / 4;
        if (words > 0)
            zero_kernel<<<(int)((words + 255) / 256), 256>>>((unsigned int*)d_out, words);
    }

    setup_kernel<<<1, 64>>>(kv, pos, h, W1, bias[0], bias[1], bias[2],
                            c0, c1, c2, bd, (int)mf);
    theta_kernel<<<NA / 2, 256>>>();
    mlp_kernel<<<NB * NK / MROWS, 256>>>();
    segsumA_kernel<<<dim3(NB, 4, 4), 512>>>();
    fsred_kernel<<<(NB * NK * ND / 4 + 255) / 256, 256>>>();
    out_kernel<<<dim3(NB, 16), 256>>>(d_out, mode, cap);
}

// round 15
// speedup vs baseline: 1.2672x; 1.2672x over previous
#include <cuda_runtime.h>
#include <cuda_bf16.h>
#include <math.h>

#define NA 8192
#define NB 32
#define NK 128
#define ND 128

__device__ float g_c[NA * NK];
__device__ float g_s[NA * NK];
__device__ float g_F[NB * NK * ND];
__device__ float g_FSre[NB * NK * ND];
__device__ float g_FSim[NB * NK * ND];
__device__ float g_pre[8][NB * NK * ND];   // segsum partials (re); reused by out
__device__ float g_pim[8][NB * NK * ND];   // segsum partials (im)
__device__ int   g_seg[NB + 1];

struct DevPtrs {
    const void *kv, *pos, *h, *W1, *b1, *W2, *b2, *W3, *b3, *batch;
    int isbf16;
    int batch64;
};
__device__ DevPtrs g_P;

__device__ __forceinline__ float ldf(const void* p, long i, int isbf) {
    if (isbf) return __bfloat162float(((const __nv_bfloat16*)p)[i]);
    return ((const float*)p)[i];
}
__device__ __forceinline__ int ldb(const void* p, int i, int b64) {
    if (b64) return (int)(((const long long*)p)[i]);
    return ((const int*)p)[i];
}
__device__ __forceinline__ float gelu_t(float x) {
    float x3 = x * x * x;
    return 0.5f * x * (1.0f + tanhf(0.7978845608028654f * fmaf(0.044715f, x3, x)));
}
__device__ static bool is_b32(const int* w) {
    int prev = -1;
    for (int j = 0; j < 128; j++) {
        int v = w[j];
        if (v < 0 || v > 63 || v < prev) return false;
        prev = v;
    }
    return true;
}
__device__ static bool is_b64(const int* w) {
    int prev = -1;
    for (int j = 0; j < 64; j++) {
        int lo = w[2*j], hi = w[2*j+1];
        if (hi != 0 || lo < 0 || lo > 63 || lo < prev) return false;
        prev = lo;
    }
    return true;
}

__global__ void setup_kernel(const void* kv, const void* pos, const void* h,
                             const void* W1, const void* b1, const void* b2,
                             const void* b3, const void* c0, const void* c1,
                             const void* c2, const void* batch_direct, int mf) {
    int tid = threadIdx.x;
    if (tid == 0) {
        DevPtrs P;
        P.kv = kv; P.pos = pos; P.h = h; P.W1 = W1;
        P.b1 = b1; P.b2 = b2; P.b3 = b3;
        const void* batch = batch_direct;
        const void* w2 = c0; const void* w3 = c1;
        if (!batch) {
            const void* cand[3] = {c0, c1, c2};
            int bi = -1;
            for (int i = 0; i < 3; i++) {
                const int* w = (const int*)cand[i];
                if (is_b32(w) || is_b64(w)) { bi = i; break; }
            }
            if (bi < 0) bi = 2;
            int nw = 0; const void* ws[2] = {0, 0};
            for (int i = 0; i < 3; i++) if (i != bi) ws[nw++] = cand[i];
            w2 = ws[0]; w3 = ws[1]; batch = cand[bi];
        }
        P.W2 = w2; P.W3 = w3; P.batch = batch;
        const int* bw = (const int*)batch;
        P.batch64 = (is_b64(bw) && !is_b32(bw)) ? 1 : 0;
        if (mf == 2) P.isbf16 = 1;
        else if (mf == 4) P.isbf16 = 0;
        else {
            const unsigned short* p16 = (const unsigned short*)pos;
            int hits = 0;
            for (int i = 0; i < 256; i++) {
                int e = (p16[i] >> 7) & 0xFF;
                if (e >= 110 && e <= 135) hits++;
            }
            P.isbf16 = (hits > 205);
        }
        g_P = P;
    }
    __syncthreads();
    if (tid <= NB) {
        const void* batch = g_P.batch;
        int b64 = g_P.batch64;
        int lo = 0, hi = NA;
        while (lo < hi) {
            int m = (lo + hi) >> 1;
            if (ldb(batch, m, b64) < tid) lo = m + 1; else hi = m;
        }
        if (lo < 0) lo = 0;
        if (lo > NA) lo = NA;
        g_seg[tid] = lo;
    }
}

__global__ void zero_kernel(unsigned int* out, long words) {
    long i = blockIdx.x * (long)blockDim.x + threadIdx.x;
    if (i < words) out[i] = 0u;
}

// ---------------------------------------------------------------------------
// theta: 2 atoms per block, 256 threads, MUFU sincos
// ---------------------------------------------------------------------------
__global__ void __launch_bounds__(256) theta_kernel() {
    const DevPtrs P = g_P;
    int n0 = blockIdx.x * 2;
    int tid = threadIdx.x;
    int a = tid >> 7;
    int k = tid & 127;
    __shared__ float p[2][3];
    __shared__ int bsh[2];
    if (tid < 6) p[tid / 3][tid % 3] = ldf(P.pos, (long)n0 * 3 + tid, P.isbf16);
    if (tid < 2) bsh[tid] = ldb(P.batch, n0 + tid, P.batch64) & 31;
    __syncthreads();
    int n = n0 + a;
    long base = ((long)bsh[a] * NK + k) * 3;
    float th = fmaf(p[a][0], ldf(P.kv, base, P.isbf16),
               fmaf(p[a][1], ldf(P.kv, base + 1, P.isbf16),
                    p[a][2] * ldf(P.kv, base + 2, P.isbf16)));
    float sv, cv;
    __sincosf(th, &sv, &cv);
    g_c[n * NK + k] = cv;
    g_s[n * NK + k] = sv;
}

// ---------------------------------------------------------------------------
// MLP v4: 8 rows/block, 512 blocks, 256 threads (measured good)
// ---------------------------------------------------------------------------
#define MROWS 8
__global__ void __launch_bounds__(256) mlp_kernel() {
    __shared__ float a1[MROWS][NK];
    __shared__ float a2[MROWS][NK];
    __shared__ float kvs[MROWS * 3];

    const DevPtrs P = g_P;
    int isbf = P.isbf16;
    int row0 = blockIdx.x * MROWS;
    int tid = threadIdx.x;
    int t = tid & 127;
    int g = tid >> 7;

    if (tid < MROWS * 3) kvs[tid] = ldf(P.kv, (long)row0 * 3 + tid, isbf);

    float w10 = ldf(P.W1, t, isbf);
    float w11 = ldf(P.W1, NK + t, isbf);
    float w12 = ldf(P.W1, 2 * NK + t, isbf);
    float bv1 = ldf(P.b1, t, isbf);
    __syncthreads();
#pragma unroll
    for (int r = 0; r < 4; r++) {
        int row = g * 4 + r;
        float x = fmaf(kvs[row*3], w10, fmaf(kvs[row*3+1], w11,
                  fmaf(kvs[row*3+2], w12, bv1)));
        a1[row][t] = gelu_t(x);
    }
    __syncthreads();
    {
        float y[4];
        float bv = ldf(P.b2, t, isbf);
#pragma unroll
        for (int r = 0; r < 4; r++) y[r] = bv;
        for (int j = 0; j < NK; j += 8) {
            float w0 = ldf(P.W2, (long)j * NK + t, isbf);
            float w1 = ldf(P.W2, (long)(j+1) * NK + t, isbf);
            float w2 = ldf(P.W2, (long)(j+2) * NK + t, isbf);
            float w3 = ldf(P.W2, (long)(j+3) * NK + t, isbf);
            float w4 = ldf(P.W2, (long)(j+4) * NK + t, isbf);
            float w5 = ldf(P.W2, (long)(j+5) * NK + t, isbf);
            float w6 = ldf(P.W2, (long)(j+6) * NK + t, isbf);
            float w7 = ldf(P.W2, (long)(j+7) * NK + t, isbf);
#pragma unroll
            for (int r = 0; r < 4; r++) {
                float4 aL = *(const float4*)&a1[g*4 + r][j];
                float4 aH = *(const float4*)&a1[g*4 + r][j+4];
                y[r] = fmaf(aL.x, w0, y[r]);
                y[r] = fmaf(aL.y, w1, y[r]);
                y[r] = fmaf(aL.z, w2, y[r]);
                y[r] = fmaf(aL.w, w3, y[r]);
                y[r] = fmaf(aH.x, w4, y[r]);
                y[r] = fmaf(aH.y, w5, y[r]);
                y[r] = fmaf(aH.z, w6, y[r]);
                y[r] = fmaf(aH.w, w7, y[r]);
            }
        }
#pragma unroll
        for (int r = 0; r < 4; r++) a2[g*4 + r][t] = gelu_t(y[r]);
    }
    __syncthreads();
    {
        float y[4];
        float bv = ldf(P.b3, t, isbf);
#pragma unroll
        for (int r = 0; r < 4; r++) y[r] = bv;
        for (int j = 0; j < NK; j += 8) {
            float w0 = ldf(P.W3, (long)j * NK + t, isbf);
            float w1 = ldf(P.W3, (long)(j+1) * NK + t, isbf);
            float w2 = ldf(P.W3, (long)(j+2) * NK + t, isbf);
            float w3 = ldf(P.W3, (long)(j+3) * NK + t, isbf);
            float w4 = ldf(P.W3, (long)(j+4) * NK + t, isbf);
            float w5 = ldf(P.W3, (long)(j+5) * NK + t, isbf);
            float w6 = ldf(P.W3, (long)(j+6) * NK + t, isbf);
            float w7 = ldf(P.W3, (long)(j+7) * NK + t, isbf);
#pragma unroll
            for (int r = 0; r < 4; r++) {
                float4 aL = *(const float4*)&a2[g*4 + r][j];
                float4 aH = *(const float4*)&a2[g*4 + r][j+4];
                y[r] = fmaf(aL.x, w0, y[r]);
                y[r] = fmaf(aL.y, w1, y[r]);
                y[r] = fmaf(aL.z, w2, y[r]);
                y[r] = fmaf(aL.w, w3, y[r]);
                y[r] = fmaf(aH.x, w4, y[r]);
                y[r] = fmaf(aH.y, w5, y[r]);
                y[r] = fmaf(aH.z, w6, y[r]);
                y[r] = fmaf(aH.w, w7, y[r]);
            }
        }
#pragma unroll
        for (int r = 0; r < 4; r++)
            g_F[(long)(row0 + g*4 + r) * NK + t] = y[r];
    }
}

// ---------------------------------------------------------------------------
// segsum stage A v2: grid (NB, 2 kchunks, 8 atom-splits) = 512 blocks, 512 thr.
// Thread owns 4d x 4k -> per atom: 9 LDS issues feed 32 FMA.
// ---------------------------------------------------------------------------
__global__ void __launch_bounds__(512) segsumA_kernel() {
    const DevPtrs P = g_P;
    int isbf = P.isbf16;
    int b = blockIdx.x;
    int k0 = blockIdx.y * 64;
    int sp = blockIdx.z;
    int tid = threadIdx.x;
    int d0 = (tid & 31) * 4;
    int kq = tid >> 5;                // 0..15 -> k = k0 + kq*4 + {0..3}
    int s0 = g_seg[b], s1 = g_seg[b + 1];
    if (s1 < s0) s1 = s0;
    int len = s1 - s0;
    int q0 = s0 + (len * sp) / 8;
    int q1 = s0 + (len * (sp + 1)) / 8;

    __shared__ float csh[32][64], ssh[32][64];
    __shared__ float hsh[32][ND];

    float aR[4][4], aI[4][4];
#pragma unroll
    for (int j = 0; j < 4; j++)
#pragma unroll
        for (int i = 0; i < 4; i++) { aR[j][i] = 0.f; aI[j][i] = 0.f; }

    for (int n0 = q0; n0 < q1; n0 += 32) {
        int cnt = min(32, q1 - n0);
        for (int i = tid; i < cnt * 16; i += 512) {
            int a = i >> 4, kk = i & 15;
            ((float4*)&csh[a][0])[kk] = *(const float4*)&g_c[(n0 + a) * NK + k0 + kk*4];
            ((float4*)&ssh[a][0])[kk] = *(const float4*)&g_s[(n0 + a) * NK + k0 + kk*4];
        }
        if (isbf) {
            for (int i = tid; i < cnt * ND; i += 512) {
                int a = i >> 7, d = i & 127;
                hsh[a][d] = __bfloat162float(((const __nv_bfloat16*)P.h)[(long)(n0 + a) * ND + d]);
            }
        } else {
            const float4* h4 = (const float4*)P.h;
            for (int i = tid; i < cnt * 32; i += 512) {
                int a = i >> 5, dq = i & 31;
                ((float4*)&hsh[a][0])[dq] = h4[(long)(n0 + a) * 32 + dq];
            }
        }
        __syncthreads();
        for (int a = 0; a < cnt; a++) {
            float4 hv = *(const float4*)&hsh[a][d0];
#pragma unroll
            for (int j = 0; j < 4; j++) {
                float c = csh[a][kq*4 + j];
                float s = ssh[a][kq*4 + j];
                aR[j][0] = fmaf(c, hv.x, aR[j][0]); aI[j][0] = fmaf(-s, hv.x, aI[j][0]);
                aR[j][1] = fmaf(c, hv.y, aR[j][1]); aI[j][1] = fmaf(-s, hv.y, aI[j][1]);
                aR[j][2] = fmaf(c, hv.z, aR[j][2]); aI[j][2] = fmaf(-s, hv.z, aI[j][2]);
                aR[j][3] = fmaf(c, hv.w, aR[j][3]); aI[j][3] = fmaf(-s, hv.w, aI[j][3]);
            }
        }
        __syncthreads();
    }
#pragma unroll
    for (int j = 0; j < 4; j++) {
        long off = ((long)b * NK + k0 + kq*4 + j) * ND + d0;
        *(float4*)&g_pre[sp][off] = make_float4(aR[j][0], aR[j][1], aR[j][2], aR[j][3]);
        *(float4*)&g_pim[sp][off] = make_float4(aI[j][0], aI[j][1], aI[j][2], aI[j][3]);
    }
}

// ---------------------------------------------------------------------------
// segsum stage B: reduce 8 partials + F multiply -> FSre/FSim
// ---------------------------------------------------------------------------
__global__ void __launch_bounds__(256) fsred_kernel() {
    long i = (blockIdx.x * 256L + threadIdx.x);     // float4 index
    if (i >= (long)NB * NK * ND / 4) return;
    float4 r = make_float4(0.f, 0.f, 0.f, 0.f);
    float4 m = make_float4(0.f, 0.f, 0.f, 0.f);
#pragma unroll
    for (int sp = 0; sp < 8; sp++) {
        float4 a = ((const float4*)g_pre[sp])[i];
        r.x += a.x; r.y += a.y; r.z += a.z; r.w += a.w;
        float4 c = ((const float4*)g_pim[sp])[i];
        m.x += c.x; m.y += c.y; m.z += c.z; m.w += c.w;
    }
    float4 f = ((const float4*)g_F)[i];
    ((float4*)g_FSre)[i] = make_float4(f.x*r.x, f.y*r.y, f.z*r.z, f.w*r.w);
    ((float4*)g_FSim)[i] = make_float4(f.x*m.x, f.y*m.y, f.z*m.z, f.w*m.w);
}

// ---------------------------------------------------------------------------
// outA (mode 0): grid (NB, 8, 2 khalf) = 512 blocks, 256 thr, 32-atom tiles,
// thread owns 4a x 4d, k in [khalf*64, khalf*64+64). Partials to scratch.
// ---------------------------------------------------------------------------
__global__ void __launch_bounds__(256) outA_kernel() {
    int b = blockIdx.x;
    int s0 = g_seg[b], s1 = g_seg[b + 1];
    if (s1 < s0) s1 = s0;
    int khalf = blockIdx.z;
    int koff = khalf * 64;
    int tid = threadIdx.x;
    int d0 = (tid & 31) * 4;
    int a0 = (tid >> 5) * 4;

    __shared__ float csh[32][64], ssh[32][64];

    const float4* FR4 = (const float4*)(g_FSre + (long)b * NK * ND);
    const float4* FI4 = (const float4*)(g_FSim + (long)b * NK * ND);
    int dq = d0 >> 2;
    float* part = (khalf == 0) ? &g_pre[0][0] : (&g_pre[0][0] + (long)NA * ND);

    for (int n0 = s0 + blockIdx.y * 32; n0 < s1; n0 += 8 * 32) {
        int cnt = min(32, s1 - n0);
        for (int i = tid; i < cnt * 16; i += 256) {
            int a = i >> 4, kk = i & 15;
            ((float4*)&csh[a][0])[kk] = *(const float4*)&g_c[(n0 + a) * NK + koff + kk*4];
            ((float4*)&ssh[a][0])[kk] = *(const float4*)&g_s[(n0 + a) * NK + koff + kk*4];
        }
        __syncthreads();

        float oR[4][4];
#pragma unroll
        for (int u = 0; u < 4; u++)
#pragma unroll
            for (int i = 0; i < 4; i++) oR[u][i] = 0.f;
#pragma unroll 2
        for (int k = 0; k < 64; k++) {
            float4 fr = FR4[(koff + k) * 32 + dq];
            float4 fi = FI4[(koff + k) * 32 + dq];
#pragma unroll
            for (int u = 0; u < 4; u++) {
                float c = csh[a0 + u][k];
                float s = ssh[a0 + u][k];
                oR[u][0] = fmaf(c, fr.x, fmaf(-s, fi.x, oR[u][0]));
                oR[u][1] = fmaf(c, fr.y, fmaf(-s, fi.y, oR[u][1]));
                oR[u][2] = fmaf(c, fr.z, fmaf(-s, fi.z, oR[u][2]));
                oR[u][3] = fmaf(c, fr.w, fmaf(-s, fi.w, oR[u][3]));
            }
        }
#pragma unroll
        for (int u = 0; u < 4; u++) {
            int a = a0 + u;
            if (a < cnt) {
                long idx = (long)(n0 + a) * ND + d0;
                *(float4*)(part + idx) =
                    make_float4(oR[u][0], oR[u][1], oR[u][2], oR[u][3]);
            }
        }
        __syncthreads();
    }
}

__global__ void __launch_bounds__(256) outred_kernel(float* __restrict__ outp,
                                                     long cap) {
    long i = blockIdx.x * 256L + threadIdx.x;       // float4 index
    if (i >= (long)NA * ND / 4) return;
    const float4* p0 = (const float4*)&g_pre[0][0];
    const float4* p1 = (const float4*)(&g_pre[0][0] + (long)NA * ND);
    float4 a = p0[i], b = p1[i];
    if (i * 4 + 4 <= cap)
        ((float4*)outp)[i] = make_float4(a.x + b.x, a.y + b.y,
                                         a.z + b.z, a.w + b.w);
}

// ---------------------------------------------------------------------------
// Fallback full out kernel for modes 1/2 (complex outputs)
// ---------------------------------------------------------------------------
__global__ void __launch_bounds__(256) outfull_kernel(void* __restrict__ outp,
                                                      int mode, long cap) {
    int b = blockIdx.x;
    int s0 = g_seg[b], s1 = g_seg[b + 1];
    if (s1 < s0) s1 = s0;
    int tid = threadIdx.x;
    int d0 = (tid & 31) * 4;
    int a0 = (tid >> 5) * 4;

    __shared__ float csh[32][NK], ssh[32][NK];

    const float4* FR4 = (const float4*)(g_FSre + (long)b * NK * ND);
    const float4* FI4 = (const float4*)(g_FSim + (long)b * NK * ND);
    int dq = d0 >> 2;

    for (int n0 = s0 + blockIdx.y * 32; n0 < s1; n0 += 8 * 32) {
        int cnt = min(32, s1 - n0);
        for (int i = tid; i < cnt * 32; i += 256) {
            int a = i >> 5, kk = i & 31;
            ((float4*)&csh[a][0])[kk] = *(const float4*)&g_c[(n0 + a) * NK + kk*4];
            ((float4*)&ssh[a][0])[kk] = *(const float4*)&g_s[(n0 + a) * NK + kk*4];
        }
        __syncthreads();
        float oR[4][4], oI[4][4];
#pragma unroll
        for (int u = 0; u < 4; u++)
#pragma unroll
            for (int i = 0; i < 4; i++) { oR[u][i] = 0.f; oI[u][i] = 0.f; }
        for (int k = 0; k < NK; k++) {
            float4 fr = FR4[k * 32 + dq];
            float4 fi = FI4[k * 32 + dq];
#pragma unroll
            for (int u = 0; u < 4; u++) {
                float c = csh[a0 + u][k];
                float s = ssh[a0 + u][k];
                oR[u][0] = fmaf(c, fr.x, fmaf(-s, fi.x, oR[u][0]));
                oR[u][1] = fmaf(c, fr.y, fmaf(-s, fi.y, oR[u][1]));
                oR[u][2] = fmaf(c, fr.z, fmaf(-s, fi.z, oR[u][2]));
                oR[u][3] = fmaf(c, fr.w, fmaf(-s, fi.w, oR[u][3]));
                oI[u][0] = fmaf(s, fr.x, fmaf(c, fi.x, oI[u][0]));
                oI[u][1] = fmaf(s, fr.y, fmaf(c, fi.y, oI[u][1]));
                oI[u][2] = fmaf(s, fr.z, fmaf(c, fi.z, oI[u][2]));
                oI[u][3] = fmaf(s, fr.w, fmaf(c, fi.w, oI[u][3]));
            }
        }
        for (int u = 0; u < 4; u++) {
            int a = a0 + u;
            if (a < cnt) {
                long row = (long)(n0 + a) * ND;
                for (int i = 0; i < 4; i++) {
                    long idx = row + d0 + i;
                    if (mode == 1) {
                        if (2 * idx + 1 < cap)
                            ((float2*)outp)[idx] = make_float2(oR[u][i], oI[u][i]);
                    } else {
                        if (idx + 1 <= cap) {
                            __nv_bfloat162 v;
                            v.x = __float2bfloat16(oR[u][i]);
                            v.y = __float2bfloat16(oI[u][i]);
                            ((__nv_bfloat162*)outp)[idx] = v;
                        }
                    }
                }
            }
        }
        __syncthreads();
    }
}

// ---------------------------------------------------------------------------
extern "C" void kernel_launch(void* const* d_in, const int* in_sizes, int n_in,
                              void* d_out, int out_size) {
    long mx = 0;
    for (int i = 0; i < n_in; i++) if ((long)in_sizes[i] > mx) mx = in_sizes[i];
    long mf;
    if (mx == 1048576L) mf = 1;
    else if (mx == 2097152L) mf = 2;
    else if (mx == 4194304L) mf = 4;
    else return;

    const void *kv = 0, *pos = 0, *h = 0, *W1 = 0;
    const void* bias[3] = {0, 0, 0};
    const void* grp[3] = {0, 0, 0};
    const void* extra = 0;
    int nb = 0, ng = 0;
    long extra_sz = (mf == 1) ? 8192 : (mf == 2) ? 65536 : 32768;
    for (int i = 0; i < n_in; i++) {
        long s = in_sizes[i];
        const void* p = d_in[i];
        if (s == 12288L * mf)        kv = p;
        else if (s == 24576L * mf)   pos = p;
        else if (s == 1048576L * mf) h = p;
        else if (s == 384L * mf)     W1 = p;
        else if (s == 128L * mf)   { if (nb < 3) bias[nb++] = p; }
        else if (s == 16384L * mf) { if (ng < 3) grp[ng++] = p; }
        else if (s == extra_sz)      extra = p;
    }
    if (!kv || !pos || !h || !W1 || nb < 3) return;

    const void *c0 = 0, *c1 = 0, *c2 = 0, *bd = 0;
    if (ng == 3)               { c0 = grp[0]; c1 = grp[1]; c2 = grp[2]; }
    else if (ng == 2 && extra) { c0 = grp[0]; c1 = grp[1]; bd = extra; }
    else return;

    int mode; long cap;
    if (out_size == 1048576)      { mode = 0; cap = 1048576L; }
    else if (out_size == 2097152) { mode = 1; cap = 2097152L; }
    else if (out_size == 8388608) { mode = 1; cap = 2097152L; }
    else if (out_size == 4194304) { mode = 2; cap = 1048576L; }
    else                          { mode = 0; cap = (long)out_size / 4; }

    if (mode != 0) {
        long words = (long)out_size / 4;
        if (words > 0)
            zero_kernel<<<(int)((words + 255) / 256), 256>>>((unsigned int*)d_out, words);
    }

    setup_kernel<<<1, 64>>>(kv, pos, h, W1, bias[0], bias[1], bias[2],
                            c0, c1, c2, bd, (int)mf);
    theta_kernel<<<NA / 2, 256>>>();
    mlp_kernel<<<NB * NK / MROWS, 256>>>();
    segsumA_kernel<<<dim3(NB, 2, 8), 512>>>();
    fsred_kernel<<<(NB * NK * ND / 4 + 255) / 256, 256>>>();
    if (mode == 0) {
        outA_kernel<<<dim3(NB, 8, 2), 256>>>();
        outred_kernel<<<(NA * ND / 4 + 255) / 256, 256>>>((float*)d_out, cap);
    } else {
        outfull_kernel<<<dim3(NB, 8), 256>>>(d_out, mode, cap);
    }
}

// round 16
// speedup vs baseline: 1.2688x; 1.0012x over previous
#include <cuda_runtime.h>
#include <cuda_bf16.h>
#include <math.h>

#define NA 8192
#define NB 32
#define NK 128
#define ND 128

__device__ float g_c[NA * NK];
__device__ float g_s[NA * NK];
__device__ float g_F[NB * NK * ND];
__device__ float g_FSre[NB * NK * ND];
__device__ float g_FSim[NB * NK * ND];
__device__ float g_pre[8][NB * NK * ND];
__device__ float g_pim[8][NB * NK * ND];
__device__ int   g_seg[NB + 1];

struct DevPtrs {
    const void *kv, *pos, *h, *W1, *b1, *W2, *b2, *W3, *b3, *batch;
    int isbf16;
    int batch64;
};
__device__ DevPtrs g_P;

__device__ __forceinline__ float ldf(const void* p, long i, int isbf) {
    if (isbf) return __bfloat162float(((const __nv_bfloat16*)p)[i]);
    return ((const float*)p)[i];
}
__device__ __forceinline__ int ldb(const void* p, int i, int b64) {
    if (b64) return (int)(((const long long*)p)[i]);
    return ((const int*)p)[i];
}
__device__ __forceinline__ float gelu_t(float x) {
    float x3 = x * x * x;
    return 0.5f * x * (1.0f + tanhf(0.7978845608028654f * fmaf(0.044715f, x3, x)));
}
__device__ static bool is_b32(const int* w) {
    int prev = -1;
    for (int j = 0; j < 128; j++) {
        int v = w[j];
        if (v < 0 || v > 63 || v < prev) return false;
        prev = v;
    }
    return true;
}
__device__ static bool is_b64(const int* w) {
    int prev = -1;
    for (int j = 0; j < 64; j++) {
        int lo = w[2*j], hi = w[2*j+1];
        if (hi != 0 || lo < 0 || lo > 63 || lo < prev) return false;
        prev = lo;
    }
    return true;
}

__global__ void setup_kernel(const void* kv, const void* pos, const void* h,
                             const void* W1, const void* b1, const void* b2,
                             const void* b3, const void* c0, const void* c1,
                             const void* c2, const void* batch_direct, int mf) {
    int tid = threadIdx.x;
    if (tid == 0) {
        DevPtrs P;
        P.kv = kv; P.pos = pos; P.h = h; P.W1 = W1;
        P.b1 = b1; P.b2 = b2; P.b3 = b3;
        const void* batch = batch_direct;
        const void* w2 = c0; const void* w3 = c1;
        if (!batch) {
            const void* cand[3] = {c0, c1, c2};
            int bi = -1;
            for (int i = 0; i < 3; i++) {
                const int* w = (const int*)cand[i];
                if (is_b32(w) || is_b64(w)) { bi = i; break; }
            }
            if (bi < 0) bi = 2;
            int nw = 0; const void* ws[2] = {0, 0};
            for (int i = 0; i < 3; i++) if (i != bi) ws[nw++] = cand[i];
            w2 = ws[0]; w3 = ws[1]; batch = cand[bi];
        }
        P.W2 = w2; P.W3 = w3; P.batch = batch;
        const int* bw = (const int*)batch;
        P.batch64 = (is_b64(bw) && !is_b32(bw)) ? 1 : 0;
        if (mf == 2) P.isbf16 = 1;
        else if (mf == 4) P.isbf16 = 0;
        else {
            const unsigned short* p16 = (const unsigned short*)pos;
            int hits = 0;
            for (int i = 0; i < 256; i++) {
                int e = (p16[i] >> 7) & 0xFF;
                if (e >= 110 && e <= 135) hits++;
            }
            P.isbf16 = (hits > 205);
        }
        g_P = P;
    }
    __syncthreads();
    if (tid <= NB) {
        const void* batch = g_P.batch;
        int b64 = g_P.batch64;
        int lo = 0, hi = NA;
        while (lo < hi) {
            int m = (lo + hi) >> 1;
            if (ldb(batch, m, b64) < tid) lo = m + 1; else hi = m;
        }
        if (lo < 0) lo = 0;
        if (lo > NA) lo = NA;
        g_seg[tid] = lo;
    }
}

__global__ void zero_kernel(unsigned int* out, long words) {
    long i = blockIdx.x * (long)blockDim.x + threadIdx.x;
    if (i < words) out[i] = 0u;
}

// ---------------------------------------------------------------------------
// theta: 2 atoms per block, 256 threads, MUFU sincos
// ---------------------------------------------------------------------------
__global__ void __launch_bounds__(256) theta_kernel() {
    const DevPtrs P = g_P;
    int n0 = blockIdx.x * 2;
    int tid = threadIdx.x;
    int a = tid >> 7;
    int k = tid & 127;
    __shared__ float p[2][3];
    __shared__ int bsh[2];
    if (tid < 6) p[tid / 3][tid % 3] = ldf(P.pos, (long)n0 * 3 + tid, P.isbf16);
    if (tid < 2) bsh[tid] = ldb(P.batch, n0 + tid, P.batch64) & 31;
    __syncthreads();
    int n = n0 + a;
    long base = ((long)bsh[a] * NK + k) * 3;
    float th = fmaf(p[a][0], ldf(P.kv, base, P.isbf16),
               fmaf(p[a][1], ldf(P.kv, base + 1, P.isbf16),
                    p[a][2] * ldf(P.kv, base + 2, P.isbf16)));
    float sv, cv;
    __sincosf(th, &sv, &cv);
    g_c[n * NK + k] = cv;
    g_s[n * NK + k] = sv;
}

// ---------------------------------------------------------------------------
// MLP v4: 8 rows/block, 512 blocks, 256 threads (measured good)
// ---------------------------------------------------------------------------
#define MROWS 8
__global__ void __launch_bounds__(256) mlp_kernel() {
    __shared__ float a1[MROWS][NK];
    __shared__ float a2[MROWS][NK];
    __shared__ float kvs[MROWS * 3];

    const DevPtrs P = g_P;
    int isbf = P.isbf16;
    int row0 = blockIdx.x * MROWS;
    int tid = threadIdx.x;
    int t = tid & 127;
    int g = tid >> 7;

    if (tid < MROWS * 3) kvs[tid] = ldf(P.kv, (long)row0 * 3 + tid, isbf);

    float w10 = ldf(P.W1, t, isbf);
    float w11 = ldf(P.W1, NK + t, isbf);
    float w12 = ldf(P.W1, 2 * NK + t, isbf);
    float bv1 = ldf(P.b1, t, isbf);
    __syncthreads();
#pragma unroll
    for (int r = 0; r < 4; r++) {
        int row = g * 4 + r;
        float x = fmaf(kvs[row*3], w10, fmaf(kvs[row*3+1], w11,
                  fmaf(kvs[row*3+2], w12, bv1)));
        a1[row][t] = gelu_t(x);
    }
    __syncthreads();
    {
        float y[4];
        float bv = ldf(P.b2, t, isbf);
#pragma unroll
        for (int r = 0; r < 4; r++) y[r] = bv;
        for (int j = 0; j < NK; j += 8) {
            float w0 = ldf(P.W2, (long)j * NK + t, isbf);
            float w1 = ldf(P.W2, (long)(j+1) * NK + t, isbf);
            float w2 = ldf(P.W2, (long)(j+2) * NK + t, isbf);
            float w3 = ldf(P.W2, (long)(j+3) * NK + t, isbf);
            float w4 = ldf(P.W2, (long)(j+4) * NK + t, isbf);
            float w5 = ldf(P.W2, (long)(j+5) * NK + t, isbf);
            float w6 = ldf(P.W2, (long)(j+6) * NK + t, isbf);
            float w7 = ldf(P.W2, (long)(j+7) * NK + t, isbf);
#pragma unroll
            for (int r = 0; r < 4; r++) {
                float4 aL = *(const float4*)&a1[g*4 + r][j];
                float4 aH = *(const float4*)&a1[g*4 + r][j+4];
                y[r] = fmaf(aL.x, w0, y[r]);
                y[r] = fmaf(aL.y, w1, y[r]);
                y[r] = fmaf(aL.z, w2, y[r]);
                y[r] = fmaf(aL.w, w3, y[r]);
                y[r] = fmaf(aH.x, w4, y[r]);
                y[r] = fmaf(aH.y, w5, y[r]);
                y[r] = fmaf(aH.z, w6, y[r]);
                y[r] = fmaf(aH.w, w7, y[r]);
            }
        }
#pragma unroll
        for (int r = 0; r < 4; r++) a2[g*4 + r][t] = gelu_t(y[r]);
    }
    __syncthreads();
    {
        float y[4];
        float bv = ldf(P.b3, t, isbf);
#pragma unroll
        for (int r = 0; r < 4; r++) y[r] = bv;
        for (int j = 0; j < NK; j += 8) {
            float w0 = ldf(P.W3, (long)j * NK + t, isbf);
            float w1 = ldf(P.W3, (long)(j+1) * NK + t, isbf);
            float w2 = ldf(P.W3, (long)(j+2) * NK + t, isbf);
            float w3 = ldf(P.W3, (long)(j+3) * NK + t, isbf);
            float w4 = ldf(P.W3, (long)(j+4) * NK + t, isbf);
            float w5 = ldf(P.W3, (long)(j+5) * NK + t, isbf);
            float w6 = ldf(P.W3, (long)(j+6) * NK + t, isbf);
            float w7 = ldf(P.W3, (long)(j+7) * NK + t, isbf);
#pragma unroll
            for (int r = 0; r < 4; r++) {
                float4 aL = *(const float4*)&a2[g*4 + r][j];
                float4 aH = *(const float4*)&a2[g*4 + r][j+4];
                y[r] = fmaf(aL.x, w0, y[r]);
                y[r] = fmaf(aL.y, w1, y[r]);
                y[r] = fmaf(aL.z, w2, y[r]);
                y[r] = fmaf(aL.w, w3, y[r]);
                y[r] = fmaf(aH.x, w4, y[r]);
                y[r] = fmaf(aH.y, w5, y[r]);
                y[r] = fmaf(aH.z, w6, y[r]);
                y[r] = fmaf(aH.w, w7, y[r]);
            }
        }
#pragma unroll
        for (int r = 0; r < 4; r++)
            g_F[(long)(row0 + g*4 + r) * NK + t] = y[r];
    }
}

// ---------------------------------------------------------------------------
// segsum stage A (measured winner R15): grid (NB, 2, 8), 512 thr, 4d x 4k
// ---------------------------------------------------------------------------
__global__ void __launch_bounds__(512) segsumA_kernel() {
    const DevPtrs P = g_P;
    int isbf = P.isbf16;
    int b = blockIdx.x;
    int k0 = blockIdx.y * 64;
    int sp = blockIdx.z;
    int tid = threadIdx.x;
    int d0 = (tid & 31) * 4;
    int kq = tid >> 5;
    int s0 = g_seg[b], s1 = g_seg[b + 1];
    if (s1 < s0) s1 = s0;
    int len = s1 - s0;
    int q0 = s0 + (len * sp) / 8;
    int q1 = s0 + (len * (sp + 1)) / 8;

    __shared__ float csh[32][64], ssh[32][64];
    __shared__ float hsh[32][ND];

    float aR[4][4], aI[4][4];
#pragma unroll
    for (int j = 0; j < 4; j++)
#pragma unroll
        for (int i = 0; i < 4; i++) { aR[j][i] = 0.f; aI[j][i] = 0.f; }

    for (int n0 = q0; n0 < q1; n0 += 32) {
        int cnt = min(32, q1 - n0);
        for (int i = tid; i < cnt * 16; i += 512) {
            int a = i >> 4, kk = i & 15;
            ((float4*)&csh[a][0])[kk] = *(const float4*)&g_c[(n0 + a) * NK + k0 + kk*4];
            ((float4*)&ssh[a][0])[kk] = *(const float4*)&g_s[(n0 + a) * NK + k0 + kk*4];
        }
        if (isbf) {
            for (int i = tid; i < cnt * ND; i += 512) {
                int a = i >> 7, d = i & 127;
                hsh[a][d] = __bfloat162float(((const __nv_bfloat16*)P.h)[(long)(n0 + a) * ND + d]);
            }
        } else {
            const float4* h4 = (const float4*)P.h;
            for (int i = tid; i < cnt * 32; i += 512) {
                int a = i >> 5, dq = i & 31;
                ((float4*)&hsh[a][0])[dq] = h4[(long)(n0 + a) * 32 + dq];
            }
        }
        __syncthreads();
        for (int a = 0; a < cnt; a++) {
            float4 hv = *(const float4*)&hsh[a][d0];
#pragma unroll
            for (int j = 0; j < 4; j++) {
                float c = csh[a][kq*4 + j];
                float s = ssh[a][kq*4 + j];
                aR[j][0] = fmaf(c, hv.x, aR[j][0]); aI[j][0] = fmaf(-s, hv.x, aI[j][0]);
                aR[j][1] = fmaf(c, hv.y, aR[j][1]); aI[j][1] = fmaf(-s, hv.y, aI[j][1]);
                aR[j][2] = fmaf(c, hv.z, aR[j][2]); aI[j][2] = fmaf(-s, hv.z, aI[j][2]);
                aR[j][3] = fmaf(c, hv.w, aR[j][3]); aI[j][3] = fmaf(-s, hv.w, aI[j][3]);
            }
        }
        __syncthreads();
    }
#pragma unroll
    for (int j = 0; j < 4; j++) {
        long off = ((long)b * NK + k0 + kq*4 + j) * ND + d0;
        *(float4*)&g_pre[sp][off] = make_float4(aR[j][0], aR[j][1], aR[j][2], aR[j][3]);
        *(float4*)&g_pim[sp][off] = make_float4(aI[j][0], aI[j][1], aI[j][2], aI[j][3]);
    }
}

__global__ void __launch_bounds__(256) fsred_kernel() {
    long i = (blockIdx.x * 256L + threadIdx.x);
    if (i >= (long)NB * NK * ND / 4) return;
    float4 r = make_float4(0.f, 0.f, 0.f, 0.f);
    float4 m = make_float4(0.f, 0.f, 0.f, 0.f);
#pragma unroll
    for (int sp = 0; sp < 8; sp++) {
        float4 a = ((const float4*)g_pre[sp])[i];
        r.x += a.x; r.y += a.y; r.z += a.z; r.w += a.w;
        float4 c = ((const float4*)g_pim[sp])[i];
        m.x += c.x; m.y += c.y; m.z += c.z; m.w += c.w;
    }
    float4 f = ((const float4*)g_F)[i];
    ((float4*)g_FSre)[i] = make_float4(f.x*r.x, f.y*r.y, f.z*r.z, f.w*r.w);
    ((float4*)g_FSim)[i] = make_float4(f.x*m.x, f.y*m.y, f.z*m.z, f.w*m.w);
}

// ---------------------------------------------------------------------------
// out via tf32 tensor cores (3xtf32 precision): mode 0 only.
// out[a][d] = sum_k c[a][k]*FSre[k][d] + s[a][k]*(-FSim[k][d])
// Block: 256 thr / 8 warps; tile 32 atoms x 128 d; K staged in 32-row chunks.
// mma.sync.m16n8k8 row.col tf32. Warp w: m-tile (w&1)*16, n-range (w>>2... )
// ---------------------------------------------------------------------------
__device__ __forceinline__ void tf32_split(float x, unsigned& hi, unsigned& lo) {
    unsigned xb = __float_as_uint(x);
    unsigned hb = xb & 0xFFFFE000u;
    hi = hb;
    lo = __float_as_uint(x - __uint_as_float(hb));
}
__device__ __forceinline__ void mma_tf32(float* d, const unsigned* a,
                                         unsigned b0, unsigned b1) {
    asm volatile(
        "mma.sync.aligned.m16n8k8.row.col.f32.tf32.tf32.f32 "
        "{%0,%1,%2,%3}, {%4,%5,%6,%7}, {%8,%9}, {%0,%1,%2,%3};\n"
        : "+f"(d[0]), "+f"(d[1]), "+f"(d[2]), "+f"(d[3])
        : "r"(a[0]), "r"(a[1]), "r"(a[2]), "r"(a[3]), "r"(b0), "r"(b1));
}

#define BS_STR 136
#define AS_STR 36
__global__ void __launch_bounds__(256) out_tc_kernel(float* __restrict__ outp,
                                                     long cap) {
    __shared__ float As[32][AS_STR];
    __shared__ float Bs[32][BS_STR];

    int b = blockIdx.x;
    int s0 = g_seg[b], s1 = g_seg[b + 1];
    if (s1 < s0) s1 = s0;
    int tid = threadIdx.x;
    int warp = tid >> 5;
    int lane = tid & 31;
    int gid = lane >> 2;              // 0..7
    int tg = lane & 3;                // 0..3
    int wm = warp & 1;                // m-tile: 0/1 (16 rows each)
    int wn = warp >> 1;               // n-range: 0..3 (32 cols each)

    const float* FR = g_FSre + (long)b * NK * ND;
    const float* FI = g_FSim + (long)b * NK * ND;

    for (int n0 = s0 + blockIdx.y * 32; n0 < s1; n0 += 8 * 32) {
        int cnt = min(32, s1 - n0);
        float acc[4][4];
#pragma unroll
        for (int nt = 0; nt < 4; nt++)
#pragma unroll
            for (int i = 0; i < 4; i++) acc[nt][i] = 0.f;

        for (int half = 0; half < 2; half++) {
            const float* Asrc = half ? g_s : g_c;
            const float* Bsrc = half ? FI : FR;
            float bsign = half ? -1.f : 1.f;
            for (int kc = 0; kc < 4; kc++) {
                int k0 = kc * 32;
                // stage A: 32 atoms x 32 k
                for (int i = tid; i < 32 * 8; i += 256) {
                    int a = i >> 3, kk = (i & 7) * 4;
                    float4 v;
                    if (a < cnt)
                        v = *(const float4*)&Asrc[(long)(n0 + a) * NK + k0 + kk];
                    else
                        v = make_float4(0.f, 0.f, 0.f, 0.f);
                    *(float4*)&As[a][kk] = v;
                }
                // stage B: 32 k x 128 d (negated for im half)
                for (int i = tid; i < 32 * 32; i += 256) {
                    int kk = i >> 5, dq = (i & 31) * 4;
                    float4 v = *(const float4*)&Bsrc[(long)(k0 + kk) * ND + dq];
                    v.x *= bsign; v.y *= bsign; v.z *= bsign; v.w *= bsign;
                    *(float4*)&Bs[kk][dq] = v;
                }
                __syncthreads();
#pragma unroll
                for (int ks = 0; ks < 4; ks++) {
                    int koff = ks * 8;
                    // A fragment (16x8): rows wm*16+gid(+8), cols koff+tg(+4)
                    float a00 = As[wm*16 + gid][koff + tg];
                    float a10 = As[wm*16 + gid + 8][koff + tg];
                    float a01 = As[wm*16 + gid][koff + tg + 4];
                    float a11 = As[wm*16 + gid + 8][koff + tg + 4];
                    unsigned ah[4], al[4];
                    tf32_split(a00, ah[0], al[0]);
                    tf32_split(a10, ah[1], al[1]);
                    tf32_split(a01, ah[2], al[2]);
                    tf32_split(a11, ah[3], al[3]);
#pragma unroll
                    for (int nt = 0; nt < 4; nt++) {
                        int ncol = wn * 32 + nt * 8 + gid;
                        float b0f = Bs[koff + tg][ncol];
                        float b1f = Bs[koff + tg + 4][ncol];
                        unsigned bh0, bl0, bh1, bl1;
                        tf32_split(b0f, bh0, bl0);
                        tf32_split(b1f, bh1, bl1);
                        mma_tf32(acc[nt], ah, bh0, bh1);
                        mma_tf32(acc[nt], ah, bl0, bl1);
                        mma_tf32(acc[nt], al, bh0, bh1);
                    }
                }
                __syncthreads();
            }
        }
        // write: rows wm*16+gid(+8), cols wn*32+nt*8+2*tg(+1)
#pragma unroll
        for (int nt = 0; nt < 4; nt++) {
            int dcol = wn * 32 + nt * 8 + 2 * tg;
            int a0r = wm * 16 + gid;
            int a1r = a0r + 8;
            if (a0r < cnt) {
                long idx = (long)(n0 + a0r) * ND + dcol;
                if (idx + 2 <= cap)
                    *(float2*)(outp + idx) = make_float2(acc[nt][0], acc[nt][1]);
            }
            if (a1r < cnt) {
                long idx = (long)(n0 + a1r) * ND + dcol;
                if (idx + 2 <= cap)
                    *(float2*)(outp + idx) = make_float2(acc[nt][2], acc[nt][3]);
            }
        }
    }
}

// ---------------------------------------------------------------------------
// Fallback full out kernel for modes 1/2 (complex outputs)
// ---------------------------------------------------------------------------
__global__ void __launch_bounds__(256) outfull_kernel(void* __restrict__ outp,
                                                      int mode, long cap) {
    int b = blockIdx.x;
    int s0 = g_seg[b], s1 = g_seg[b + 1];
    if (s1 < s0) s1 = s0;
    int tid = threadIdx.x;
    int d0 = (tid & 31) * 4;
    int a0 = (tid >> 5) * 4;

    __shared__ float csh[32][NK], ssh[32][NK];

    const float4* FR4 = (const float4*)(g_FSre + (long)b * NK * ND);
    const float4* FI4 = (const float4*)(g_FSim + (long)b * NK * ND);
    int dq = d0 >> 2;

    for (int n0 = s0 + blockIdx.y * 32; n0 < s1; n0 += 8 * 32) {
        int cnt = min(32, s1 - n0);
        for (int i = tid; i < cnt * 32; i += 256) {
            int a = i >> 5, kk = i & 31;
            ((float4*)&csh[a][0])[kk] = *(const float4*)&g_c[(n0 + a) * NK + kk*4];
            ((float4*)&ssh[a][0])[kk] = *(const float4*)&g_s[(n0 + a) * NK + kk*4];
        }
        __syncthreads();
        float oR[4][4], oI[4][4];
#pragma unroll
        for (int u = 0; u < 4; u++)
#pragma unroll
            for (int i = 0; i < 4; i++) { oR[u][i] = 0.f; oI[u][i] = 0.f; }
        for (int k = 0; k < NK; k++) {
            float4 fr = FR4[k * 32 + dq];
            float4 fi = FI4[k * 32 + dq];
#pragma unroll
            for (int u = 0; u < 4; u++) {
                float c = csh[a0 + u][k];
                float s = ssh[a0 + u][k];
                oR[u][0] = fmaf(c, fr.x, fmaf(-s, fi.x, oR[u][0]));
                oR[u][1] = fmaf(c, fr.y, fmaf(-s, fi.y, oR[u][1]));
                oR[u][2] = fmaf(c, fr.z, fmaf(-s, fi.z, oR[u][2]));
                oR[u][3] = fmaf(c, fr.w, fmaf(-s, fi.w, oR[u][3]));
                oI[u][0] = fmaf(s, fr.x, fmaf(c, fi.x, oI[u][0]));
                oI[u][1] = fmaf(s, fr.y, fmaf(c, fi.y, oI[u][1]));
                oI[u][2] = fmaf(s, fr.z, fmaf(c, fi.z, oI[u][2]));
                oI[u][3] = fmaf(s, fr.w, fmaf(c, fi.w, oI[u][3]));
            }
        }
        for (int u = 0; u < 4; u++) {
            int a = a0 + u;
            if (a < cnt) {
                long row = (long)(n0 + a) * ND;
                for (int i = 0; i < 4; i++) {
                    long idx = row + d0 + i;
                    if (mode == 1) {
                        if (2 * idx + 1 < cap)
                            ((float2*)outp)[idx] = make_float2(oR[u][i], oI[u][i]);
                    } else {
                        if (idx + 1 <= cap) {
                            __nv_bfloat162 v;
                            v.x = __float2bfloat16(oR[u][i]);
                            v.y = __float2bfloat16(oI[u][i]);
                            ((__nv_bfloat162*)outp)[idx] = v;
                        }
                    }
                }
            }
        }
        __syncthreads();
    }
}

// ---------------------------------------------------------------------------
extern "C" void kernel_launch(void* const* d_in, const int* in_sizes, int n_in,
                              void* d_out, int out_size) {
    long mx = 0;
    for (int i = 0; i < n_in; i++) if ((long)in_sizes[i] > mx) mx = in_sizes[i];
    long mf;
    if (mx == 1048576L) mf = 1;
    else if (mx == 2097152L) mf = 2;
    else if (mx == 4194304L) mf = 4;
    else return;

    const void *kv = 0, *pos = 0, *h = 0, *W1 = 0;
    const void* bias[3] = {0, 0, 0};
    const void* grp[3] = {0, 0, 0};
    const void* extra = 0;
    int nb = 0, ng = 0;
    long extra_sz = (mf == 1) ? 8192 : (mf == 2) ? 65536 : 32768;
    for (int i = 0; i < n_in; i++) {
        long s = in_sizes[i];
        const void* p = d_in[i];
        if (s == 12288L * mf)        kv = p;
        else if (s == 24576L * mf)   pos = p;
        else if (s == 1048576L * mf) h = p;
        else if (s == 384L * mf)     W1 = p;
        else if (s == 128L * mf)   { if (nb < 3) bias[nb++] = p; }
        else if (s == 16384L * mf) { if (ng < 3) grp[ng++] = p; }
        else if (s == extra_sz)      extra = p;
    }
    if (!kv || !pos || !h || !W1 || nb < 3) return;

    const void *c0 = 0, *c1 = 0, *c2 = 0, *bd = 0;
    if (ng == 3)               { c0 = grp[0]; c1 = grp[1]; c2 = grp[2]; }
    else if (ng == 2 && extra) { c0 = grp[0]; c1 = grp[1]; bd = extra; }
    else return;

    int mode; long cap;
    if (out_size == 1048576)      { mode = 0; cap = 1048576L; }
    else if (out_size == 2097152) { mode = 1; cap = 2097152L; }
    else if (out_size == 8388608) { mode = 1; cap = 2097152L; }
    else if (out_size == 4194304) { mode = 2; cap = 1048576L; }
    else                          { mode = 0; cap = (long)out_size / 4; }

    if (mode != 0) {
        long words = (long)out_size / 4;
        if (words > 0)
            zero_kernel<<<(int)((words + 255) / 256), 256>>>((unsigned int*)d_out, words);
    }

    setup_kernel<<<1, 64>>>(kv, pos, h, W1, bias[0], bias[1], bias[2],
                            c0, c1, c2, bd, (int)mf);
    theta_kernel<<<NA / 2, 256>>>();
    mlp_kernel<<<NB * NK / MROWS, 256>>>();
    segsumA_kernel<<<dim3(NB, 2, 8), 512>>>();
    fsred_kernel<<<(NB * NK * ND / 4 + 255) / 256, 256>>>();
    if (mode == 0) {
        out_tc_kernel<<<dim3(NB, 8), 256>>>((float*)d_out, cap);
    } else {
        outfull_kernel<<<dim3(NB, 8), 256>>>(d_out, mode, cap);
    }
}

// round 17
// speedup vs baseline: 1.2940x; 1.0199x over previous
#include <cuda_runtime.h>
#include <cuda_bf16.h>
#include <math.h>

#define NA 8192
#define NB 32
#define NK 128
#define ND 128
#define NSPLIT 4

__device__ float g_c[NA * NK];
__device__ float g_s[NA * NK];
__device__ float g_F[NB * NK * ND];
__device__ float g_FSre[NB * NK * ND];
__device__ float g_FSim[NB * NK * ND];
__device__ float g_pre[NSPLIT][NB * NK * ND];
__device__ float g_pim[NSPLIT][NB * NK * ND];
__device__ int   g_seg[NB + 1];

struct DevPtrs {
    const void *kv, *pos, *h, *W1, *b1, *W2, *b2, *W3, *b3, *batch;
    int isbf16;
    int batch64;
};
__device__ DevPtrs g_P;

__device__ __forceinline__ float ldf(const void* p, long i, int isbf) {
    if (isbf) return __bfloat162float(((const __nv_bfloat16*)p)[i]);
    return ((const float*)p)[i];
}
__device__ __forceinline__ int ldb(const void* p, int i, int b64) {
    if (b64) return (int)(((const long long*)p)[i]);
    return ((const int*)p)[i];
}
__device__ __forceinline__ float gelu_t(float x) {
    float x3 = x * x * x;
    return 0.5f * x * (1.0f + tanhf(0.7978845608028654f * fmaf(0.044715f, x3, x)));
}
__device__ static bool is_b32(const int* w) {
    int prev = -1;
    for (int j = 0; j < 128; j++) {
        int v = w[j];
        if (v < 0 || v > 63 || v < prev) return false;
        prev = v;
    }
    return true;
}
__device__ static bool is_b64(const int* w) {
    int prev = -1;
    for (int j = 0; j < 64; j++) {
        int lo = w[2*j], hi = w[2*j+1];
        if (hi != 0 || lo < 0 || lo > 63 || lo < prev) return false;
        prev = lo;
    }
    return true;
}

__global__ void setup_kernel(const void* kv, const void* pos, const void* h,
                             const void* W1, const void* b1, const void* b2,
                             const void* b3, const void* c0, const void* c1,
                             const void* c2, const void* batch_direct, int mf) {
    int tid = threadIdx.x;
    if (tid == 0) {
        DevPtrs P;
        P.kv = kv; P.pos = pos; P.h = h; P.W1 = W1;
        P.b1 = b1; P.b2 = b2; P.b3 = b3;
        const void* batch = batch_direct;
        const void* w2 = c0; const void* w3 = c1;
        if (!batch) {
            const void* cand[3] = {c0, c1, c2};
            int bi = -1;
            for (int i = 0; i < 3; i++) {
                const int* w = (const int*)cand[i];
                if (is_b32(w) || is_b64(w)) { bi = i; break; }
            }
            if (bi < 0) bi = 2;
            int nw = 0; const void* ws[2] = {0, 0};
            for (int i = 0; i < 3; i++) if (i != bi) ws[nw++] = cand[i];
            w2 = ws[0]; w3 = ws[1]; batch = cand[bi];
        }
        P.W2 = w2; P.W3 = w3; P.batch = batch;
        const int* bw = (const int*)batch;
        P.batch64 = (is_b64(bw) && !is_b32(bw)) ? 1 : 0;
        if (mf == 2) P.isbf16 = 1;
        else if (mf == 4) P.isbf16 = 0;
        else {
            const unsigned short* p16 = (const unsigned short*)pos;
            int hits = 0;
            for (int i = 0; i < 256; i++) {
                int e = (p16[i] >> 7) & 0xFF;
                if (e >= 110 && e <= 135) hits++;
            }
            P.isbf16 = (hits > 205);
        }
        g_P = P;
    }
    __syncthreads();
    if (tid <= NB) {
        const void* batch = g_P.batch;
        int b64 = g_P.batch64;
        int lo = 0, hi = NA;
        while (lo < hi) {
            int m = (lo + hi) >> 1;
            if (ldb(batch, m, b64) < tid) lo = m + 1; else hi = m;
        }
        if (lo < 0) lo = 0;
        if (lo > NA) lo = NA;
        g_seg[tid] = lo;
    }
}

__global__ void zero_kernel(unsigned int* out, long words) {
    long i = blockIdx.x * (long)blockDim.x + threadIdx.x;
    if (i < words) out[i] = 0u;
}

// ---------------------------------------------------------------------------
__global__ void __launch_bounds__(256) theta_kernel() {
    const DevPtrs P = g_P;
    int n0 = blockIdx.x * 2;
    int tid = threadIdx.x;
    int a = tid >> 7;
    int k = tid & 127;
    __shared__ float p[2][3];
    __shared__ int bsh[2];
    if (tid < 6) p[tid / 3][tid % 3] = ldf(P.pos, (long)n0 * 3 + tid, P.isbf16);
    if (tid < 2) bsh[tid] = ldb(P.batch, n0 + tid, P.batch64) & 31;
    __syncthreads();
    int n = n0 + a;
    long base = ((long)bsh[a] * NK + k) * 3;
    float th = fmaf(p[a][0], ldf(P.kv, base, P.isbf16),
               fmaf(p[a][1], ldf(P.kv, base + 1, P.isbf16),
                    p[a][2] * ldf(P.kv, base + 2, P.isbf16)));
    float sv, cv;
    __sincosf(th, &sv, &cv);
    g_c[n * NK + k] = cv;
    g_s[n * NK + k] = sv;
}

// ---------------------------------------------------------------------------
#define MROWS 8
__global__ void __launch_bounds__(256) mlp_kernel() {
    __shared__ float a1[MROWS][NK];
    __shared__ float a2[MROWS][NK];
    __shared__ float kvs[MROWS * 3];

    const DevPtrs P = g_P;
    int isbf = P.isbf16;
    int row0 = blockIdx.x * MROWS;
    int tid = threadIdx.x;
    int t = tid & 127;
    int g = tid >> 7;

    if (tid < MROWS * 3) kvs[tid] = ldf(P.kv, (long)row0 * 3 + tid, isbf);

    float w10 = ldf(P.W1, t, isbf);
    float w11 = ldf(P.W1, NK + t, isbf);
    float w12 = ldf(P.W1, 2 * NK + t, isbf);
    float bv1 = ldf(P.b1, t, isbf);
    __syncthreads();
#pragma unroll
    for (int r = 0; r < 4; r++) {
        int row = g * 4 + r;
        float x = fmaf(kvs[row*3], w10, fmaf(kvs[row*3+1], w11,
                  fmaf(kvs[row*3+2], w12, bv1)));
        a1[row][t] = gelu_t(x);
    }
    __syncthreads();
    {
        float y[4];
        float bv = ldf(P.b2, t, isbf);
#pragma unroll
        for (int r = 0; r < 4; r++) y[r] = bv;
        for (int j = 0; j < NK; j += 8) {
            float w0 = ldf(P.W2, (long)j * NK + t, isbf);
            float w1 = ldf(P.W2, (long)(j+1) * NK + t, isbf);
            float w2 = ldf(P.W2, (long)(j+2) * NK + t, isbf);
            float w3 = ldf(P.W2, (long)(j+3) * NK + t, isbf);
            float w4 = ldf(P.W2, (long)(j+4) * NK + t, isbf);
            float w5 = ldf(P.W2, (long)(j+5) * NK + t, isbf);
            float w6 = ldf(P.W2, (long)(j+6) * NK + t, isbf);
            float w7 = ldf(P.W2, (long)(j+7) * NK + t, isbf);
#pragma unroll
            for (int r = 0; r < 4; r++) {
                float4 aL = *(const float4*)&a1[g*4 + r][j];
                float4 aH = *(const float4*)&a1[g*4 + r][j+4];
                y[r] = fmaf(aL.x, w0, y[r]);
                y[r] = fmaf(aL.y, w1, y[r]);
                y[r] = fmaf(aL.z, w2, y[r]);
                y[r] = fmaf(aL.w, w3, y[r]);
                y[r] = fmaf(aH.x, w4, y[r]);
                y[r] = fmaf(aH.y, w5, y[r]);
                y[r] = fmaf(aH.z, w6, y[r]);
                y[r] = fmaf(aH.w, w7, y[r]);
            }
        }
#pragma unroll
        for (int r = 0; r < 4; r++) a2[g*4 + r][t] = gelu_t(y[r]);
    }
    __syncthreads();
    {
        float y[4];
        float bv = ldf(P.b3, t, isbf);
#pragma unroll
        for (int r = 0; r < 4; r++) y[r] = bv;
        for (int j = 0; j < NK; j += 8) {
            float w0 = ldf(P.W3, (long)j * NK + t, isbf);
            float w1 = ldf(P.W3, (long)(j+1) * NK + t, isbf);
            float w2 = ldf(P.W3, (long)(j+2) * NK + t, isbf);
            float w3 = ldf(P.W3, (long)(j+3) * NK + t, isbf);
            float w4 = ldf(P.W3, (long)(j+4) * NK + t, isbf);
            float w5 = ldf(P.W3, (long)(j+5) * NK + t, isbf);
            float w6 = ldf(P.W3, (long)(j+6) * NK + t, isbf);
            float w7 = ldf(P.W3, (long)(j+7) * NK + t, isbf);
#pragma unroll
            for (int r = 0; r < 4; r++) {
                float4 aL = *(const float4*)&a2[g*4 + r][j];
                float4 aH = *(const float4*)&a2[g*4 + r][j+4];
                y[r] = fmaf(aL.x, w0, y[r]);
                y[r] = fmaf(aL.y, w1, y[r]);
                y[r] = fmaf(aL.z, w2, y[r]);
                y[r] = fmaf(aL.w, w3, y[r]);
                y[r] = fmaf(aH.x, w4, y[r]);
                y[r] = fmaf(aH.y, w5, y[r]);
                y[r] = fmaf(aH.z, w6, y[r]);
                y[r] = fmaf(aH.w, w7, y[r]);
            }
        }
#pragma unroll
        for (int r = 0; r < 4; r++)
            g_F[(long)(row0 + g*4 + r) * NK + t] = y[r];
    }
}

// ---------------------------------------------------------------------------
// tf32 helpers (mapping validated by out_tc in R16)
// ---------------------------------------------------------------------------
__device__ __forceinline__ void tf32_split(float x, unsigned& hi, unsigned& lo) {
    unsigned xb = __float_as_uint(x);
    unsigned hb = xb & 0xFFFFE000u;
    hi = hb;
    lo = __float_as_uint(x - __uint_as_float(hb));
}
__device__ __forceinline__ void mma_tf32(float* d, const unsigned* a,
                                         unsigned b0, unsigned b1) {
    asm volatile(
        "mma.sync.aligned.m16n8k8.row.col.f32.tf32.tf32.f32 "
        "{%0,%1,%2,%3}, {%4,%5,%6,%7}, {%8,%9}, {%0,%1,%2,%3};\n"
        : "+f"(d[0]), "+f"(d[1]), "+f"(d[2]), "+f"(d[3])
        : "r"(a[0]), "r"(a[1]), "r"(a[2]), "r"(a[3]), "r"(b0), "r"(b1));
}

// ---------------------------------------------------------------------------
// segsum via tf32 TC: S_re[k][d] = sum_a c[a][k] h[a][d]; S_im with -s.
// grid (NB, NSPLIT), 512 thr / 16 warps. Warp: k-rows (warp&7)*16, d-half
// (warp>>3)*64. Dynamic smem: c/s/h tiles, 32 x stride-136 (conflict-free).
// ---------------------------------------------------------------------------
#define PS 136
__global__ void __launch_bounds__(512) segsum_tc_kernel() {
    extern __shared__ float sm[];
    float* csh = sm;                  // [32][PS]
    float* ssh = sm + 32 * PS;        // negated s
    float* hsh = sm + 64 * PS;

    const DevPtrs P = g_P;
    int isbf = P.isbf16;
    int b = blockIdx.x;
    int sp = blockIdx.y;
    int tid = threadIdx.x;
    int warp = tid >> 5, lane = tid & 31;
    int gid = lane >> 2, tg = lane & 3;
    int kbase = (warp & 7) * 16;
    int dhalf = (warp >> 3) * 64;
    int s0 = g_seg[b], s1 = g_seg[b + 1];
    if (s1 < s0) s1 = s0;
    int len = s1 - s0;
    int q0 = s0 + (len * sp) / NSPLIT;
    int q1 = s0 + (len * (sp + 1)) / NSPLIT;

    float accR[8][4], accI[8][4];
#pragma unroll
    for (int nt = 0; nt < 8; nt++)
#pragma unroll
        for (int i = 0; i < 4; i++) { accR[nt][i] = 0.f; accI[nt][i] = 0.f; }

    for (int n0 = q0; n0 < q1; n0 += 32) {
        int cnt = min(32, q1 - n0);
        for (int i = tid; i < 32 * 32; i += 512) {
            int a = i >> 5, q = (i & 31) * 4;
            float4 vc, vs;
            if (a < cnt) {
                vc = *(const float4*)&g_c[(long)(n0 + a) * NK + q];
                vs = *(const float4*)&g_s[(long)(n0 + a) * NK + q];
                vs.x = -vs.x; vs.y = -vs.y; vs.z = -vs.z; vs.w = -vs.w;
            } else {
                vc = make_float4(0.f, 0.f, 0.f, 0.f);
                vs = vc;
            }
            *(float4*)&csh[a * PS + q] = vc;
            *(float4*)&ssh[a * PS + q] = vs;
        }
        if (isbf) {
            for (int i = tid; i < 32 * ND; i += 512) {
                int a = i >> 7, d = i & 127;
                hsh[a * PS + d] = (a < cnt)
                    ? __bfloat162float(((const __nv_bfloat16*)P.h)[(long)(n0 + a) * ND + d])
                    : 0.f;
            }
        } else {
            for (int i = tid; i < 32 * 32; i += 512) {
                int a = i >> 5, q = (i & 31) * 4;
                float4 v = (a < cnt)
                    ? *(const float4*)&((const float*)P.h)[(long)(n0 + a) * ND + q]
                    : make_float4(0.f, 0.f, 0.f, 0.f);
                *(float4*)&hsh[a * PS + q] = v;
            }
        }
        __syncthreads();
#pragma unroll
        for (int sub = 0; sub < 4; sub++) {
            int ab = sub * 8;
            // A fragments (transposed reads, conflict-free via PS padding)
            float c00 = csh[(ab + tg) * PS + kbase + gid];
            float c10 = csh[(ab + tg) * PS + kbase + gid + 8];
            float c01 = csh[(ab + tg + 4) * PS + kbase + gid];
            float c11 = csh[(ab + tg + 4) * PS + kbase + gid + 8];
            float s00 = ssh[(ab + tg) * PS + kbase + gid];
            float s10 = ssh[(ab + tg) * PS + kbase + gid + 8];
            float s01 = ssh[(ab + tg + 4) * PS + kbase + gid];
            float s11 = ssh[(ab + tg + 4) * PS + kbase + gid + 8];
            unsigned ch[4], cl[4], sh_[4], sl_[4];
            tf32_split(c00, ch[0], cl[0]);
            tf32_split(c10, ch[1], cl[1]);
            tf32_split(c01, ch[2], cl[2]);
            tf32_split(c11, ch[3], cl[3]);
            tf32_split(s00, sh_[0], sl_[0]);
            tf32_split(s10, sh_[1], sl_[1]);
            tf32_split(s01, sh_[2], sl_[2]);
            tf32_split(s11, sh_[3], sl_[3]);
#pragma unroll
            for (int nt = 0; nt < 8; nt++) {
                int dcol = dhalf + nt * 8 + gid;
                float b0f = hsh[(ab + tg) * PS + dcol];
                float b1f = hsh[(ab + tg + 4) * PS + dcol];
                unsigned bh0, bl0, bh1, bl1;
                tf32_split(b0f, bh0, bl0);
                tf32_split(b1f, bh1, bl1);
                mma_tf32(accR[nt], ch, bh0, bh1);
                mma_tf32(accR[nt], ch, bl0, bl1);
                mma_tf32(accR[nt], cl, bh0, bh1);
                mma_tf32(accI[nt], sh_, bh0, bh1);
                mma_tf32(accI[nt], sh_, bl0, bl1);
                mma_tf32(accI[nt], sl_, bh0, bh1);
            }
        }
        __syncthreads();
    }
#pragma unroll
    for (int nt = 0; nt < 8; nt++) {
        int dcol = dhalf + nt * 8 + 2 * tg;
        long off0 = ((long)b * NK + kbase + gid) * ND + dcol;
        long off1 = ((long)b * NK + kbase + gid + 8) * ND + dcol;
        *(float2*)&g_pre[sp][off0] = make_float2(accR[nt][0], accR[nt][1]);
        *(float2*)&g_pre[sp][off1] = make_float2(accR[nt][2], accR[nt][3]);
        *(float2*)&g_pim[sp][off0] = make_float2(accI[nt][0], accI[nt][1]);
        *(float2*)&g_pim[sp][off1] = make_float2(accI[nt][2], accI[nt][3]);
    }
}

__global__ void __launch_bounds__(256) fsred_kernel() {
    long i = (blockIdx.x * 256L + threadIdx.x);
    if (i >= (long)NB * NK * ND / 4) return;
    float4 r = make_float4(0.f, 0.f, 0.f, 0.f);
    float4 m = make_float4(0.f, 0.f, 0.f, 0.f);
#pragma unroll
    for (int sp = 0; sp < NSPLIT; sp++) {
        float4 a = ((const float4*)g_pre[sp])[i];
        r.x += a.x; r.y += a.y; r.z += a.z; r.w += a.w;
        float4 c = ((const float4*)g_pim[sp])[i];
        m.x += c.x; m.y += c.y; m.z += c.z; m.w += c.w;
    }
    float4 f = ((const float4*)g_F)[i];
    ((float4*)g_FSre)[i] = make_float4(f.x*r.x, f.y*r.y, f.z*r.z, f.w*r.w);
    ((float4*)g_FSim)[i] = make_float4(f.x*m.x, f.y*m.y, f.z*m.z, f.w*m.w);
}

// ---------------------------------------------------------------------------
// out via tf32 tensor cores (measured R16)
// ---------------------------------------------------------------------------
#define BS_STR 136
#define AS_STR 36
__global__ void __launch_bounds__(256) out_tc_kernel(float* __restrict__ outp,
                                                     long cap) {
    __shared__ float As[32][AS_STR];
    __shared__ float Bs[32][BS_STR];

    int b = blockIdx.x;
    int s0 = g_seg[b], s1 = g_seg[b + 1];
    if (s1 < s0) s1 = s0;
    int tid = threadIdx.x;
    int warp = tid >> 5;
    int lane = tid & 31;
    int gid = lane >> 2;
    int tg = lane & 3;
    int wm = warp & 1;
    int wn = warp >> 1;

    const float* FR = g_FSre + (long)b * NK * ND;
    const float* FI = g_FSim + (long)b * NK * ND;

    for (int n0 = s0 + blockIdx.y * 32; n0 < s1; n0 += 8 * 32) {
        int cnt = min(32, s1 - n0);
        float acc[4][4];
#pragma unroll
        for (int nt = 0; nt < 4; nt++)
#pragma unroll
            for (int i = 0; i < 4; i++) acc[nt][i] = 0.f;

        for (int half = 0; half < 2; half++) {
            const float* Asrc = half ? g_s : g_c;
            const float* Bsrc = half ? FI : FR;
            float bsign = half ? -1.f : 1.f;
            for (int kc = 0; kc < 4; kc++) {
                int k0 = kc * 32;
                for (int i = tid; i < 32 * 8; i += 256) {
                    int a = i >> 3, kk = (i & 7) * 4;
                    float4 v;
                    if (a < cnt)
                        v = *(const float4*)&Asrc[(long)(n0 + a) * NK + k0 + kk];
                    else
                        v = make_float4(0.f, 0.f, 0.f, 0.f);
                    *(float4*)&As[a][kk] = v;
                }
                for (int i = tid; i < 32 * 32; i += 256) {
                    int kk = i >> 5, dq = (i & 31) * 4;
                    float4 v = *(const float4*)&Bsrc[(long)(k0 + kk) * ND + dq];
                    v.x *= bsign; v.y *= bsign; v.z *= bsign; v.w *= bsign;
                    *(float4*)&Bs[kk][dq] = v;
                }
                __syncthreads();
#pragma unroll
                for (int ks = 0; ks < 4; ks++) {
                    int koff = ks * 8;
                    float a00 = As[wm*16 + gid][koff + tg];
                    float a10 = As[wm*16 + gid + 8][koff + tg];
                    float a01 = As[wm*16 + gid][koff + tg + 4];
                    float a11 = As[wm*16 + gid + 8][koff + tg + 4];
                    unsigned ah[4], al[4];
                    tf32_split(a00, ah[0], al[0]);
                    tf32_split(a10, ah[1], al[1]);
                    tf32_split(a01, ah[2], al[2]);
                    tf32_split(a11, ah[3], al[3]);
#pragma unroll
                    for (int nt = 0; nt < 4; nt++) {
                        int ncol = wn * 32 + nt * 8 + gid;
                        float b0f = Bs[koff + tg][ncol];
                        float b1f = Bs[koff + tg + 4][ncol];
                        unsigned bh0, bl0, bh1, bl1;
                        tf32_split(b0f, bh0, bl0);
                        tf32_split(b1f, bh1, bl1);
                        mma_tf32(acc[nt], ah, bh0, bh1);
                        mma_tf32(acc[nt], ah, bl0, bl1);
                        mma_tf32(acc[nt], al, bh0, bh1);
                    }
                }
                __syncthreads();
            }
        }
#pragma unroll
        for (int nt = 0; nt < 4; nt++) {
            int dcol = wn * 32 + nt * 8 + 2 * tg;
            int a0r = wm * 16 + gid;
            int a1r = a0r + 8;
            if (a0r < cnt) {
                long idx = (long)(n0 + a0r) * ND + dcol;
                if (idx + 2 <= cap)
                    *(float2*)(outp + idx) = make_float2(acc[nt][0], acc[nt][1]);
            }
            if (a1r < cnt) {
                long idx = (long)(n0 + a1r) * ND + dcol;
                if (idx + 2 <= cap)
                    *(float2*)(outp + idx) = make_float2(acc[nt][2], acc[nt][3]);
            }
        }
    }
}

// ---------------------------------------------------------------------------
// Fallback full out kernel for modes 1/2 (complex outputs)
// ---------------------------------------------------------------------------
__global__ void __launch_bounds__(256) outfull_kernel(void* __restrict__ outp,
                                                      int mode, long cap) {
    int b = blockIdx.x;
    int s0 = g_seg[b], s1 = g_seg[b + 1];
    if (s1 < s0) s1 = s0;
    int tid = threadIdx.x;
    int d0 = (tid & 31) * 4;
    int a0 = (tid >> 5) * 4;

    __shared__ float csh[32][NK], ssh[32][NK];

    const float4* FR4 = (const float4*)(g_FSre + (long)b * NK * ND);
    const float4* FI4 = (const float4*)(g_FSim + (long)b * NK * ND);
    int dq = d0 >> 2;

    for (int n0 = s0 + blockIdx.y * 32; n0 < s1; n0 += 8 * 32) {
        int cnt = min(32, s1 - n0);
        for (int i = tid; i < cnt * 32; i += 256) {
            int a = i >> 5, kk = i & 31;
            ((float4*)&csh[a][0])[kk] = *(const float4*)&g_c[(n0 + a) * NK + kk*4];
            ((float4*)&ssh[a][0])[kk] = *(const float4*)&g_s[(n0 + a) * NK + kk*4];
        }
        __syncthreads();
        float oR[4][4], oI[4][4];
#pragma unroll
        for (int u = 0; u < 4; u++)
#pragma unroll
            for (int i = 0; i < 4; i++) { oR[u][i] = 0.f; oI[u][i] = 0.f; }
        for (int k = 0; k < NK; k++) {
            float4 fr = FR4[k * 32 + dq];
            float4 fi = FI4[k * 32 + dq];
#pragma unroll
            for (int u = 0; u < 4; u++) {
                float c = csh[a0 + u][k];
                float s = ssh[a0 + u][k];
                oR[u][0] = fmaf(c, fr.x, fmaf(-s, fi.x, oR[u][0]));
                oR[u][1] = fmaf(c, fr.y, fmaf(-s, fi.y, oR[u][1]));
                oR[u][2] = fmaf(c, fr.z, fmaf(-s, fi.z, oR[u][2]));
                oR[u][3] = fmaf(c, fr.w, fmaf(-s, fi.w, oR[u][3]));
                oI[u][0] = fmaf(s, fr.x, fmaf(c, fi.x, oI[u][0]));
                oI[u][1] = fmaf(s, fr.y, fmaf(c, fi.y, oI[u][1]));
                oI[u][2] = fmaf(s, fr.z, fmaf(c, fi.z, oI[u][2]));
                oI[u][3] = fmaf(s, fr.w, fmaf(c, fi.w, oI[u][3]));
            }
        }
        for (int u = 0; u < 4; u++) {
            int a = a0 + u;
            if (a < cnt) {
                long row = (long)(n0 + a) * ND;
                for (int i = 0; i < 4; i++) {
                    long idx = row + d0 + i;
                    if (mode == 1) {
                        if (2 * idx + 1 < cap)
                            ((float2*)outp)[idx] = make_float2(oR[u][i], oI[u][i]);
                    } else {
                        if (idx + 1 <= cap) {
                            __nv_bfloat162 v;
                            v.x = __float2bfloat16(oR[u][i]);
                            v.y = __float2bfloat16(oI[u][i]);
                            ((__nv_bfloat162*)outp)[idx] = v;
                        }
                    }
                }
            }
        }
        __syncthreads();
    }
}

// ---------------------------------------------------------------------------
extern "C" void kernel_launch(void* const* d_in, const int* in_sizes, int n_in,
                              void* d_out, int out_size) {
    long mx = 0;
    for (int i = 0; i < n_in; i++) if ((long)in_sizes[i] > mx) mx = in_sizes[i];
    long mf;
    if (mx == 1048576L) mf = 1;
    else if (mx == 2097152L) mf = 2;
    else if (mx == 4194304L) mf = 4;
    else return;

    const void *kv = 0, *pos = 0, *h = 0, *W1 = 0;
    const void* bias[3] = {0, 0, 0};
    const void* grp[3] = {0, 0, 0};
    const void* extra = 0;
    int nb = 0, ng = 0;
    long extra_sz = (mf == 1) ? 8192 : (mf == 2) ? 65536 : 32768;
    for (int i = 0; i < n_in; i++) {
        long s = in_sizes[i];
        const void* p = d_in[i];
        if (s == 12288L * mf)        kv = p;
        else if (s == 24576L * mf)   pos = p;
        else if (s == 1048576L * mf) h = p;
        else if (s == 384L * mf)     W1 = p;
        else if (s == 128L * mf)   { if (nb < 3) bias[nb++] = p; }
        else if (s == 16384L * mf) { if (ng < 3) grp[ng++] = p; }
        else if (s == extra_sz)      extra = p;
    }
    if (!kv || !pos || !h || !W1 || nb < 3) return;

    const void *c0 = 0, *c1 = 0, *c2 = 0, *bd = 0;
    if (ng == 3)               { c0 = grp[0]; c1 = grp[1]; c2 = grp[2]; }
    else if (ng == 2 && extra) { c0 = grp[0]; c1 = grp[1]; bd = extra; }
    else return;

    int mode; long cap;
    if (out_size == 1048576)      { mode = 0; cap = 1048576L; }
    else if (out_size == 2097152) { mode = 1; cap = 2097152L; }
    else if (out_size == 8388608) { mode = 1; cap = 2097152L; }
    else if (out_size == 4194304) { mode = 2; cap = 1048576L; }
    else                          { mode = 0; cap = (long)out_size / 4; }

    if (mode != 0) {
        long words = (long)out_size / 4;
        if (words > 0)
            zero_kernel<<<(int)((words + 255) / 256), 256>>>((unsigned int*)d_out, words);
    }

    setup_kernel<<<1, 64>>>(kv, pos, h, W1, bias[0], bias[1], bias[2],
                            c0, c1, c2, bd, (int)mf);
    theta_kernel<<<NA / 2, 256>>>();
    mlp_kernel<<<NB * NK / MROWS, 256>>>();

    int smem_seg = 96 * PS * 4;      // 3 tiles x 32 rows x PS floats
    cudaFuncSetAttribute(segsum_tc_kernel,
                         cudaFuncAttributeMaxDynamicSharedMemorySize, smem_seg);
    segsum_tc_kernel<<<dim3(NB, NSPLIT), 512, smem_seg>>>();
    fsred_kernel<<<(NB * NK * ND / 4 + 255) / 256, 256>>>();
    if (mode == 0) {
        out_tc_kernel<<<dim3(NB, 8), 256>>>((float*)d_out, cap);
    } else {
        outfull_kernel<<<dim3(NB, 8), 256>>>(d_out, mode, cap);
    }
}